// round 3
// baseline (speedup 1.0000x reference)
#include <cuda_runtime.h>
#include <math.h>

#define NR 512
#define CS 384
#define CZ 128
#define CH 16
#define NH 12
#define DQ 192
#define DO 1728
#define DF 1536

#define OFF_S  0
#define OFF_Q  196608
#define OFF_K  294912
#define OFF_V  393216
#define OFF_O  491520
#define OFF_T  1376256
#define OFF_C  2162688
#define OFF_CO 2359296
#define OFF_B  2360832
#define BIAS_L 3145728

__device__ float g_buf[OFF_B + 8L * BIAS_L];

// ------------------------------------------------------------------ init
__global__ void k_init(const float* __restrict__ s_in) {
    int i = blockIdx.x * blockDim.x + threadIdx.x;
    if (i < NR * CS) g_buf[OFF_S + i] = s_in[i];
    if (i < NR * 3)  g_buf[OFF_CO + i] = 0.f;
}

// ------------------------------------------- bias_z precompute, 8 layers
// g_buf[OFF_B + l*BIAS_L + (i*512+j)*12 + h] = z[i,j,:]@Wb[l][:,h] + bb[l][h]
__global__ void __launch_bounds__(128) k_biaspre(const float* __restrict__ z,
                                                 const float* __restrict__ Wb,
                                                 const float* __restrict__ bb) {
    __shared__ float sWb[CZ * 48];
    __shared__ float sbb[48];
    __shared__ float sz[32][132];

    const int half = blockIdx.y;
    const int t = threadIdx.x;

    for (int idx = t; idx < CZ * 48; idx += 128) {
        int c = idx / 48, gh = idx - c * 48, g = gh / 12, hh = gh - g * 12;
        sWb[idx] = Wb[((half * 4 + g) * CZ + c) * NH + hh];
    }
    if (t < 48) sbb[t] = bb[half * 48 + t];

    const int rr = t >> 2, g = t & 3, l = half * 4 + g;
    const int r0 = blockIdx.x * 256;
    float* obase = g_buf + OFF_B + (size_t)l * BIAS_L;

    for (int chunk = 0; chunk < 256; chunk += 32) {
        __syncthreads();
        const float4* zsrc = (const float4*)(z + (size_t)(r0 + chunk) * CZ);
        for (int idx = t; idx < 32 * 32; idx += 128)
            *(float4*)&sz[idx >> 5][(idx & 31) * 4] = zsrc[idx];
        __syncthreads();

        float acc[12];
        #pragma unroll
        for (int hh = 0; hh < 12; ++hh) acc[hh] = sbb[g * 12 + hh];

        #pragma unroll 4
        for (int c = 0; c < CZ; ++c) {
            float zv = sz[rr][c];
            const float4* wp = (const float4*)(sWb + c * 48 + g * 12);
            float4 w0 = wp[0], w1 = wp[1], w2 = wp[2];
            acc[0] = fmaf(zv, w0.x, acc[0]);  acc[1] = fmaf(zv, w0.y, acc[1]);
            acc[2] = fmaf(zv, w0.z, acc[2]);  acc[3] = fmaf(zv, w0.w, acc[3]);
            acc[4] = fmaf(zv, w1.x, acc[4]);  acc[5] = fmaf(zv, w1.y, acc[5]);
            acc[6] = fmaf(zv, w1.z, acc[6]);  acc[7] = fmaf(zv, w1.w, acc[7]);
            acc[8] = fmaf(zv, w2.x, acc[8]);  acc[9] = fmaf(zv, w2.y, acc[9]);
            acc[10] = fmaf(zv, w2.z, acc[10]); acc[11] = fmaf(zv, w2.w, acc[11]);
        }
        float* op = obase + (size_t)(r0 + chunk + rr) * NH;
        *(float4*)(op + 0) = make_float4(acc[0], acc[1], acc[2], acc[3]);
        *(float4*)(op + 4) = make_float4(acc[4], acc[5], acc[6], acc[7]);
        *(float4*)(op + 8) = make_float4(acc[8], acc[9], acc[10], acc[11]);
    }
}

// --------------------------------------------------------- tiled GEMM
// C(512xN) = A(512xK) @ W(KxN) + bias  [optional ReLU]; blockIdx.z picks W set
template <int RELU>
__global__ void __launch_bounds__(128) k_gemm(
    int a_off,
    const float* __restrict__ W0, const float* __restrict__ W1, const float* __restrict__ W2,
    const float* __restrict__ b0, const float* __restrict__ b1, const float* __restrict__ b2,
    int c_off, int c_zstride, int K, int N)
{
    const float* W = W0; const float* bias = b0;
    if (blockIdx.z == 1) { W = W1; bias = b1; }
    else if (blockIdx.z == 2) { W = W2; bias = b2; }
    float* C = g_buf + c_off + blockIdx.z * c_zstride;

    __shared__ float As[32][32];
    __shared__ float Bs[32][32];

    const int t = threadIdx.x;
    const int r = t >> 2, cq = (t & 3) << 3;
    const int ty = t >> 3, tx = t & 7;

    const float* Ap = g_buf + a_off + (size_t)(blockIdx.y * 32) * K;
    const float* Wp = W + blockIdx.x * 32;

    float acc[2][4] = {};

    for (int k0 = 0; k0 < K; k0 += 32) {
        float4 a0 = *(const float4*)(Ap + (size_t)r * K + k0 + cq);
        float4 a1 = *(const float4*)(Ap + (size_t)r * K + k0 + cq + 4);
        float4 w0 = *(const float4*)(Wp + (size_t)(k0 + r) * N + cq);
        float4 w1 = *(const float4*)(Wp + (size_t)(k0 + r) * N + cq + 4);
        As[cq + 0][r] = a0.x; As[cq + 1][r] = a0.y; As[cq + 2][r] = a0.z; As[cq + 3][r] = a0.w;
        As[cq + 4][r] = a1.x; As[cq + 5][r] = a1.y; As[cq + 6][r] = a1.z; As[cq + 7][r] = a1.w;
        *(float4*)&Bs[r][cq]     = w0;
        *(float4*)&Bs[r][cq + 4] = w1;
        __syncthreads();

        #pragma unroll
        for (int kk = 0; kk < 32; ++kk) {
            float a0v = As[kk][ty * 2], a1v = As[kk][ty * 2 + 1];
            float4 b = *(const float4*)&Bs[kk][tx * 4];
            acc[0][0] = fmaf(a0v, b.x, acc[0][0]); acc[0][1] = fmaf(a0v, b.y, acc[0][1]);
            acc[0][2] = fmaf(a0v, b.z, acc[0][2]); acc[0][3] = fmaf(a0v, b.w, acc[0][3]);
            acc[1][0] = fmaf(a1v, b.x, acc[1][0]); acc[1][1] = fmaf(a1v, b.y, acc[1][1]);
            acc[1][2] = fmaf(a1v, b.z, acc[1][2]); acc[1][3] = fmaf(a1v, b.w, acc[1][3]);
        }
        __syncthreads();
    }

    const int row = blockIdx.y * 32 + ty * 2;
    const int col = blockIdx.x * 32 + tx * 4;
    float4 bv = *(const float4*)(bias + col);
    #pragma unroll
    for (int mi = 0; mi < 2; ++mi) {
        float4 out;
        out.x = acc[mi][0] + bv.x; out.y = acc[mi][1] + bv.y;
        out.z = acc[mi][2] + bv.z; out.w = acc[mi][3] + bv.w;
        if (RELU) {
            out.x = fmaxf(out.x, 0.f); out.y = fmaxf(out.y, 0.f);
            out.z = fmaxf(out.z, 0.f); out.w = fmaxf(out.w, 0.f);
        }
        *(float4*)(C + (size_t)(row + mi) * N + col) = out;
    }
}

// --------------------------------------------------- fused attention row
__global__ void __launch_bounds__(384) k_attn(const float* __restrict__ z, int l) {
    __shared__ float s_logit[NR * NH];   // 24 KB
    __shared__ float s_red[2][CZ][NH];   // 12 KB
    __shared__ float s_ms[NR];
    __shared__ float s_q[DQ];

    const int i = blockIdx.x;
    const int t = threadIdx.x;

    if (t < DQ) s_q[t] = g_buf[OFF_Q + i * DQ + t];
    const float cx = g_buf[OFF_CO + i * 3 + 0];
    const float cy = g_buf[OFF_CO + i * 3 + 1];
    const float cz2 = g_buf[OFF_CO + i * 3 + 2];
    for (int j = t; j < NR; j += 384) {
        float dx = g_buf[OFF_CO + j * 3 + 0] - cx;
        float dy = g_buf[OFF_CO + j * 3 + 1] - cy;
        float dz = g_buf[OFF_CO + j * 3 + 2] - cz2;
        float sq = dx * dx + dy * dy + dz * dz;
        s_ms[j] = (sq <= 25.f) ? 1.f : ((sq <= 225.f) ? 0.3f : 0.05f);
    }
    __syncthreads();

    // logits = q.k/4 + bias_z + ms
    const float* bias = g_buf + OFF_B + (size_t)l * BIAS_L + (size_t)i * (NR * NH);
    #pragma unroll 2
    for (int idx = t; idx < NR * NH; idx += 384) {
        int j = idx / 12, h = idx - j * 12;
        const float* kp = g_buf + OFF_K + j * DQ + h * CH;
        const float4* qp = (const float4*)(s_q + h * CH);
        float4 k0 = *(const float4*)(kp + 0), k1 = *(const float4*)(kp + 4);
        float4 k2 = *(const float4*)(kp + 8), k3 = *(const float4*)(kp + 12);
        float4 q0 = qp[0], q1 = qp[1], q2 = qp[2], q3 = qp[3];
        float d = k0.x * q0.x;
        d = fmaf(k0.y, q0.y, d); d = fmaf(k0.z, q0.z, d); d = fmaf(k0.w, q0.w, d);
        d = fmaf(k1.x, q1.x, d); d = fmaf(k1.y, q1.y, d); d = fmaf(k1.z, q1.z, d); d = fmaf(k1.w, q1.w, d);
        d = fmaf(k2.x, q2.x, d); d = fmaf(k2.y, q2.y, d); d = fmaf(k2.z, q2.z, d); d = fmaf(k2.w, q2.w, d);
        d = fmaf(k3.x, q3.x, d); d = fmaf(k3.y, q3.y, d); d = fmaf(k3.z, q3.z, d); d = fmaf(k3.w, q3.w, d);
        s_logit[idx] = fmaf(d, 0.25f, bias[idx] + s_ms[j]);
    }
    __syncthreads();

    // softmax over j, warp per head
    {
        int h = t >> 5, lane = t & 31;
        float m = -1e30f;
        for (int j = lane; j < NR; j += 32) m = fmaxf(m, s_logit[j * 12 + h]);
        #pragma unroll
        for (int o = 16; o; o >>= 1) m = fmaxf(m, __shfl_xor_sync(0xffffffffu, m, o));
        float ssum = 0.f;
        for (int j = lane; j < NR; j += 32) {
            float e = __expf(s_logit[j * 12 + h] - m);
            s_logit[j * 12 + h] = e; ssum += e;
        }
        #pragma unroll
        for (int o = 16; o; o >>= 1) ssum += __shfl_xor_sync(0xffffffffu, ssum, o);
        float inv = 1.f / ssum;
        for (int j = lane; j < NR; j += 32) s_logit[j * 12 + h] *= inv;
    }
    __syncthreads();

    // pair[h][c] = sum_j w[j][h] * z[i,j,c] — each z element loaded once, 12 heads reuse
    {
        const int jj = t >> 7, c = t & 127;
        float pa[12] = {};
        const float* zp = z + (size_t)i * (NR * CZ);
        for (int j = jj; j < NR; j += 3) {
            float zv = zp[j * CZ + c];
            const float4* wr = (const float4*)(s_logit + j * 12);
            float4 w0 = wr[0], w1 = wr[1], w2 = wr[2];
            pa[0] = fmaf(w0.x, zv, pa[0]);  pa[1] = fmaf(w0.y, zv, pa[1]);
            pa[2] = fmaf(w0.z, zv, pa[2]);  pa[3] = fmaf(w0.w, zv, pa[3]);
            pa[4] = fmaf(w1.x, zv, pa[4]);  pa[5] = fmaf(w1.y, zv, pa[5]);
            pa[6] = fmaf(w1.z, zv, pa[6]);  pa[7] = fmaf(w1.w, zv, pa[7]);
            pa[8] = fmaf(w2.x, zv, pa[8]);  pa[9] = fmaf(w2.y, zv, pa[9]);
            pa[10] = fmaf(w2.z, zv, pa[10]); pa[11] = fmaf(w2.w, zv, pa[11]);
        }
        if (jj) {
            #pragma unroll
            for (int h = 0; h < 12; ++h) s_red[jj - 1][c][h] = pa[h];
        }
        __syncthreads();
        if (jj == 0) {
            #pragma unroll
            for (int h = 0; h < 12; ++h)
                g_buf[OFF_O + i * DO + h * 144 + 16 + c] =
                    pa[h] + s_red[0][c][h] + s_red[1][c][h];
        }
    }

    // scalar[h][c] = sum_j w[j][h] * v[j,h,c] — warp per head
    {
        const int h = t >> 5, lane = t & 31;
        const int cc = lane & 15, part = lane >> 4;
        float acc = 0.f;
        for (int j = part; j < NR; j += 2)
            acc = fmaf(s_logit[j * 12 + h], g_buf[OFF_V + j * DQ + h * CH + cc], acc);
        acc += __shfl_down_sync(0xffffffffu, acc, 16);
        if (lane < 16) g_buf[OFF_O + i * DO + h * 144 + cc] = acc;
    }
}

// --------------------------------- layernorm (+ optional coords update)
__global__ void __launch_bounds__(128) k_ln(const float* __restrict__ g,
                                            const float* __restrict__ b,
                                            const float* __restrict__ Wu,
                                            const float* __restrict__ bu,
                                            int fuse) {
    const int i = blockIdx.x, t = threadIdx.x, base = i * CS;

    float x0 = g_buf[OFF_S + base + t]       + g_buf[OFF_C + base + t];
    float x1 = g_buf[OFF_S + base + t + 128] + g_buf[OFF_C + base + t + 128];
    float x2 = g_buf[OFF_S + base + t + 256] + g_buf[OFF_C + base + t + 256];

    float sum = x0 + x1 + x2;
    float sq  = x0 * x0 + x1 * x1 + x2 * x2;
    #pragma unroll
    for (int o = 16; o; o >>= 1) {
        sum += __shfl_xor_sync(0xffffffffu, sum, o);
        sq  += __shfl_xor_sync(0xffffffffu, sq, o);
    }
    __shared__ float sred[8];
    const int w = t >> 5, lane = t & 31;
    if (lane == 0) { sred[w] = sum; sred[4 + w] = sq; }
    __syncthreads();
    sum = sred[0] + sred[1] + sred[2] + sred[3];
    sq  = sred[4] + sred[5] + sred[6] + sred[7];
    float mu  = sum * (1.f / CS);
    float var = sq * (1.f / CS) - mu * mu;
    float rs  = rsqrtf(var + 1e-5f);

    float y0 = (x0 - mu) * rs * g[t]       + b[t];
    float y1 = (x1 - mu) * rs * g[t + 128] + b[t + 128];
    float y2 = (x2 - mu) * rs * g[t + 256] + b[t + 256];
    g_buf[OFF_S + base + t]       = y0;
    g_buf[OFF_S + base + t + 128] = y1;
    g_buf[OFF_S + base + t + 256] = y2;

    if (fuse) {
        float p0 = y0 * Wu[t * 6 + 0] + y1 * Wu[(t + 128) * 6 + 0] + y2 * Wu[(t + 256) * 6 + 0];
        float p1 = y0 * Wu[t * 6 + 1] + y1 * Wu[(t + 128) * 6 + 1] + y2 * Wu[(t + 256) * 6 + 1];
        float p2 = y0 * Wu[t * 6 + 2] + y1 * Wu[(t + 128) * 6 + 2] + y2 * Wu[(t + 256) * 6 + 2];
        #pragma unroll
        for (int o = 16; o; o >>= 1) {
            p0 += __shfl_xor_sync(0xffffffffu, p0, o);
            p1 += __shfl_xor_sync(0xffffffffu, p1, o);
            p2 += __shfl_xor_sync(0xffffffffu, p2, o);
        }
        __shared__ float sp[12];
        if (lane == 0) { sp[w] = p0; sp[4 + w] = p1; sp[8 + w] = p2; }
        __syncthreads();
        if (t == 0) {
            g_buf[OFF_CO + i * 3 + 0] += sp[0] + sp[1] + sp[2]  + sp[3]  + bu[0];
            g_buf[OFF_CO + i * 3 + 1] += sp[4] + sp[5] + sp[6]  + sp[7]  + bu[1];
            g_buf[OFF_CO + i * 3 + 2] += sp[8] + sp[9] + sp[10] + sp[11] + bu[2];
        }
    }
}

__global__ void k_out(float* __restrict__ out) {
    int i = blockIdx.x * blockDim.x + threadIdx.x;
    if (i < NR * 3) out[i] = g_buf[OFF_CO + i];
}

// ---------------------------------------------------------------- launch
extern "C" void kernel_launch(void* const* d_in, const int* in_sizes, int n_in,
                              void* d_out, int out_size) {
    const float* s   = (const float*)d_in[0];
    const float* z   = (const float*)d_in[1];
    const float* Wq  = (const float*)d_in[2];
    const float* bq  = (const float*)d_in[3];
    const float* Wk  = (const float*)d_in[4];
    const float* bk  = (const float*)d_in[5];
    const float* Wv  = (const float*)d_in[6];
    const float* bv  = (const float*)d_in[7];
    const float* Wb  = (const float*)d_in[8];
    const float* bb  = (const float*)d_in[9];
    const float* Wo  = (const float*)d_in[10];
    const float* bo  = (const float*)d_in[11];
    const float* Wt1 = (const float*)d_in[12];
    const float* bt1 = (const float*)d_in[13];
    const float* Wt2 = (const float*)d_in[14];
    const float* bt2 = (const float*)d_in[15];
    const float* Wu  = (const float*)d_in[16];
    const float* bu  = (const float*)d_in[17];
    const float* lng = (const float*)d_in[18];
    const float* lnb = (const float*)d_in[19];

    k_init<<<768, 256>>>(s);
    k_biaspre<<<dim3(1024, 2), 128>>>(z, Wb, bb);

    for (int r = 0; r < 2; ++r) {
        for (int l = 0; l < 8; ++l) {
            k_gemm<0><<<dim3(6, 16, 3), 128>>>(OFF_S,
                Wq + (size_t)l * CS * DQ, Wk + (size_t)l * CS * DQ, Wv + (size_t)l * CS * DQ,
                bq + l * DQ, bk + l * DQ, bv + l * DQ,
                OFF_Q, NR * DQ, CS, DQ);
            k_attn<<<512, 384>>>(z, l);
            k_gemm<0><<<dim3(12, 16, 1), 128>>>(OFF_O,
                Wo + (size_t)l * DO * CS, nullptr, nullptr,
                bo + l * CS, nullptr, nullptr,
                OFF_C, 0, DO, CS);
            k_ln<<<512, 128>>>(lng + (2 * l) * CS, lnb + (2 * l) * CS, nullptr, nullptr, 0);
            k_gemm<1><<<dim3(48, 16, 1), 128>>>(OFF_S,
                Wt1 + (size_t)l * CS * DF, nullptr, nullptr,
                bt1 + l * DF, nullptr, nullptr,
                OFF_T, 0, CS, DF);
            k_gemm<0><<<dim3(12, 16, 1), 128>>>(OFF_T,
                Wt2 + (size_t)l * DF * CS, nullptr, nullptr,
                bt2 + l * CS, nullptr, nullptr,
                OFF_C, 0, DF, CS);
            k_ln<<<512, 128>>>(lng + (2 * l + 1) * CS, lnb + (2 * l + 1) * CS,
                               Wu + (size_t)l * CS * 6, bu + l * 6, 1);
        }
    }
    k_out<<<6, 256>>>((float*)d_out);
}

// round 4
// speedup vs baseline: 1.0899x; 1.0899x over previous
#include <cuda_runtime.h>
#include <math.h>

#define NR 512
#define CS 384
#define CZ 128
#define CH 16
#define NH 12
#define DQ 192
#define DO 1728
#define DF 1536

#define OFF_S  0
#define OFF_Q  196608
#define OFF_K  294912
#define OFF_V  393216
#define OFF_O  491520
#define OFF_T  1376256
#define OFF_C  2162688
#define OFF_C2 2359296
#define OFF_CO 2555904
#define OFF_B  2557440
#define BIAS_L 3145728

__device__ float g_buf[OFF_B + 8L * BIAS_L];

// ------------------------------------------------------------------ init
__global__ void k_init(const float* __restrict__ s_in) {
    int i = blockIdx.x * blockDim.x + threadIdx.x;
    if (i < NR * CS) g_buf[OFF_S + i] = s_in[i];
    if (i < NR * 3)  g_buf[OFF_CO + i] = 0.f;
}

// ------------------------------------------- bias_z precompute, 8 layers
__global__ void __launch_bounds__(128) k_biaspre(const float* __restrict__ z,
                                                 const float* __restrict__ Wb,
                                                 const float* __restrict__ bb) {
    __shared__ float sWb[CZ * 48];
    __shared__ float sbb[48];
    __shared__ float sz[32][132];

    const int half = blockIdx.y;
    const int t = threadIdx.x;

    for (int idx = t; idx < CZ * 48; idx += 128) {
        int c = idx / 48, gh = idx - c * 48, g = gh / 12, hh = gh - g * 12;
        sWb[idx] = Wb[((half * 4 + g) * CZ + c) * NH + hh];
    }
    if (t < 48) sbb[t] = bb[half * 48 + t];

    const int rr = t >> 2, g = t & 3, l = half * 4 + g;
    const int r0 = blockIdx.x * 256;
    float* obase = g_buf + OFF_B + (size_t)l * BIAS_L;

    for (int chunk = 0; chunk < 256; chunk += 32) {
        __syncthreads();
        const float4* zsrc = (const float4*)(z + (size_t)(r0 + chunk) * CZ);
        for (int idx = t; idx < 32 * 32; idx += 128)
            *(float4*)&sz[idx >> 5][(idx & 31) * 4] = zsrc[idx];
        __syncthreads();

        float acc[12];
        #pragma unroll
        for (int hh = 0; hh < 12; ++hh) acc[hh] = sbb[g * 12 + hh];

        #pragma unroll 4
        for (int c = 0; c < CZ; ++c) {
            float zv = sz[rr][c];
            const float4* wp = (const float4*)(sWb + c * 48 + g * 12);
            float4 w0 = wp[0], w1 = wp[1], w2 = wp[2];
            acc[0] = fmaf(zv, w0.x, acc[0]);  acc[1] = fmaf(zv, w0.y, acc[1]);
            acc[2] = fmaf(zv, w0.z, acc[2]);  acc[3] = fmaf(zv, w0.w, acc[3]);
            acc[4] = fmaf(zv, w1.x, acc[4]);  acc[5] = fmaf(zv, w1.y, acc[5]);
            acc[6] = fmaf(zv, w1.z, acc[6]);  acc[7] = fmaf(zv, w1.w, acc[7]);
            acc[8] = fmaf(zv, w2.x, acc[8]);  acc[9] = fmaf(zv, w2.y, acc[9]);
            acc[10] = fmaf(zv, w2.z, acc[10]); acc[11] = fmaf(zv, w2.w, acc[11]);
        }
        float* op = obase + (size_t)(r0 + chunk + rr) * NH;
        *(float4*)(op + 0) = make_float4(acc[0], acc[1], acc[2], acc[3]);
        *(float4*)(op + 4) = make_float4(acc[4], acc[5], acc[6], acc[7]);
        *(float4*)(op + 8) = make_float4(acc[8], acc[9], acc[10], acc[11]);
    }
}

// --------------------------------------------------------- tiled GEMM
// BM=32, BN=64, BK=16, 128 threads, 4x4 micro-tile.
// SPLITK=0: blockIdx.z selects weight set {W0,W1,W2}.
// SPLITK=1: blockIdx.z selects K-partition (W0 only); bias added by part 0.
template <int RELU, int SPLITK>
__global__ void __launch_bounds__(128) k_gemm(
    int a_off,
    const float* __restrict__ W0, const float* __restrict__ W1, const float* __restrict__ W2,
    const float* __restrict__ b0, const float* __restrict__ b1, const float* __restrict__ b2,
    int c_off, int c_zstride, int Kfull, int Kpart, int N)
{
    const int zb = blockIdx.z;
    const float* W; const float* bias; int ashift;
    if (SPLITK) {
        W = W0 + (size_t)zb * Kpart * N;
        bias = (zb == 0) ? b0 : nullptr;
        ashift = zb * Kpart;
    } else {
        W = (zb == 1) ? W1 : (zb == 2) ? W2 : W0;
        bias = (zb == 1) ? b1 : (zb == 2) ? b2 : b0;
        ashift = 0;
    }
    float* C = g_buf + c_off + (size_t)zb * c_zstride;

    __shared__ float As[16][36];
    __shared__ float Bs[16][64];

    const int t = threadIdx.x;
    const int lm = t >> 2, lk = (t & 3) << 2;        // A load: row, k-quad
    const int bk = t >> 3, bn8 = (t & 7) << 3;       // B load: k-row, 8 cols
    const int ty = t >> 4, tx = t & 15;              // compute

    const float* Ap = g_buf + a_off + (size_t)(blockIdx.y * 32 + lm) * Kfull + ashift + lk;
    const float* Wp = W + (size_t)bk * N + blockIdx.x * 64 + bn8;

    float acc[4][4] = {};

    for (int k0 = 0; k0 < Kpart; k0 += 16) {
        float4 av = *(const float4*)(Ap + k0);
        float4 w0v = *(const float4*)(Wp + (size_t)k0 * N);
        float4 w1v = *(const float4*)(Wp + (size_t)k0 * N + 4);
        As[lk + 0][lm] = av.x; As[lk + 1][lm] = av.y;
        As[lk + 2][lm] = av.z; As[lk + 3][lm] = av.w;
        *(float4*)&Bs[bk][bn8]     = w0v;
        *(float4*)&Bs[bk][bn8 + 4] = w1v;
        __syncthreads();

        #pragma unroll
        for (int kk = 0; kk < 16; ++kk) {
            float4 a = *(const float4*)&As[kk][ty * 4];
            float4 b = *(const float4*)&Bs[kk][tx * 4];
            acc[0][0] = fmaf(a.x, b.x, acc[0][0]); acc[0][1] = fmaf(a.x, b.y, acc[0][1]);
            acc[0][2] = fmaf(a.x, b.z, acc[0][2]); acc[0][3] = fmaf(a.x, b.w, acc[0][3]);
            acc[1][0] = fmaf(a.y, b.x, acc[1][0]); acc[1][1] = fmaf(a.y, b.y, acc[1][1]);
            acc[1][2] = fmaf(a.y, b.z, acc[1][2]); acc[1][3] = fmaf(a.y, b.w, acc[1][3]);
            acc[2][0] = fmaf(a.z, b.x, acc[2][0]); acc[2][1] = fmaf(a.z, b.y, acc[2][1]);
            acc[2][2] = fmaf(a.z, b.z, acc[2][2]); acc[2][3] = fmaf(a.z, b.w, acc[2][3]);
            acc[3][0] = fmaf(a.w, b.x, acc[3][0]); acc[3][1] = fmaf(a.w, b.y, acc[3][1]);
            acc[3][2] = fmaf(a.w, b.z, acc[3][2]); acc[3][3] = fmaf(a.w, b.w, acc[3][3]);
        }
        __syncthreads();
    }

    const int row = blockIdx.y * 32 + ty * 4;
    const int col = blockIdx.x * 64 + tx * 4;
    float4 bv = make_float4(0.f, 0.f, 0.f, 0.f);
    if (bias) bv = *(const float4*)(bias + col);
    #pragma unroll
    for (int mi = 0; mi < 4; ++mi) {
        float4 out;
        out.x = acc[mi][0] + bv.x; out.y = acc[mi][1] + bv.y;
        out.z = acc[mi][2] + bv.z; out.w = acc[mi][3] + bv.w;
        if (RELU) {
            out.x = fmaxf(out.x, 0.f); out.y = fmaxf(out.y, 0.f);
            out.z = fmaxf(out.z, 0.f); out.w = fmaxf(out.w, 0.f);
        }
        *(float4*)(C + (size_t)(row + mi) * N + col) = out;
    }
}

// --------------------------------------------------- fused attention row
__global__ void __launch_bounds__(384) k_attn(const float* __restrict__ z, int l) {
    __shared__ float s_logit[NR * NH];   // 24 KB
    __shared__ float s_red[2][CZ][NH];   // 12 KB
    __shared__ float s_ms[NR];
    __shared__ float s_q[DQ];

    const int i = blockIdx.x;
    const int t = threadIdx.x;

    if (t < DQ) s_q[t] = g_buf[OFF_Q + i * DQ + t];
    const float cx = g_buf[OFF_CO + i * 3 + 0];
    const float cy = g_buf[OFF_CO + i * 3 + 1];
    const float cz2 = g_buf[OFF_CO + i * 3 + 2];
    for (int j = t; j < NR; j += 384) {
        float dx = g_buf[OFF_CO + j * 3 + 0] - cx;
        float dy = g_buf[OFF_CO + j * 3 + 1] - cy;
        float dz = g_buf[OFF_CO + j * 3 + 2] - cz2;
        float sq = dx * dx + dy * dy + dz * dz;
        s_ms[j] = (sq <= 25.f) ? 1.f : ((sq <= 225.f) ? 0.3f : 0.05f);
    }
    __syncthreads();

    // logits = q.k/4 + bias_z + ms
    const float* bias = g_buf + OFF_B + (size_t)l * BIAS_L + (size_t)i * (NR * NH);
    #pragma unroll 4
    for (int idx = t; idx < NR * NH; idx += 384) {
        int j = idx / 12, h = idx - j * 12;
        const float* kp = g_buf + OFF_K + j * DQ + h * CH;
        const float4* qp = (const float4*)(s_q + h * CH);
        float4 k0 = *(const float4*)(kp + 0), k1 = *(const float4*)(kp + 4);
        float4 k2 = *(const float4*)(kp + 8), k3 = *(const float4*)(kp + 12);
        float4 q0 = qp[0], q1 = qp[1], q2 = qp[2], q3 = qp[3];
        float d = k0.x * q0.x;
        d = fmaf(k0.y, q0.y, d); d = fmaf(k0.z, q0.z, d); d = fmaf(k0.w, q0.w, d);
        d = fmaf(k1.x, q1.x, d); d = fmaf(k1.y, q1.y, d); d = fmaf(k1.z, q1.z, d); d = fmaf(k1.w, q1.w, d);
        d = fmaf(k2.x, q2.x, d); d = fmaf(k2.y, q2.y, d); d = fmaf(k2.z, q2.z, d); d = fmaf(k2.w, q2.w, d);
        d = fmaf(k3.x, q3.x, d); d = fmaf(k3.y, q3.y, d); d = fmaf(k3.z, q3.z, d); d = fmaf(k3.w, q3.w, d);
        s_logit[idx] = fmaf(d, 0.25f, bias[idx] + s_ms[j]);
    }
    __syncthreads();

    // softmax over j, warp per head
    {
        int h = t >> 5, lane = t & 31;
        float m = -1e30f;
        for (int j = lane; j < NR; j += 32) m = fmaxf(m, s_logit[j * 12 + h]);
        #pragma unroll
        for (int o = 16; o; o >>= 1) m = fmaxf(m, __shfl_xor_sync(0xffffffffu, m, o));
        float ssum = 0.f;
        for (int j = lane; j < NR; j += 32) {
            float e = __expf(s_logit[j * 12 + h] - m);
            s_logit[j * 12 + h] = e; ssum += e;
        }
        #pragma unroll
        for (int o = 16; o; o >>= 1) ssum += __shfl_xor_sync(0xffffffffu, ssum, o);
        float inv = 1.f / ssum;
        for (int j = lane; j < NR; j += 32) s_logit[j * 12 + h] *= inv;
    }
    __syncthreads();

    // pair[h][c] = sum_j w[j][h] * z[i,j,c] — z streamed once, 12 heads reuse;
    // unroll 4 for memory-level parallelism (HBM latency hiding)
    {
        const int jj = t >> 7, c = t & 127;
        float pa[12] = {};
        const float* zp = z + (size_t)i * (NR * CZ);
        #pragma unroll 4
        for (int j = jj; j < NR; j += 3) {
            float zv = zp[j * CZ + c];
            const float4* wr = (const float4*)(s_logit + j * 12);
            float4 w0 = wr[0], w1 = wr[1], w2 = wr[2];
            pa[0] = fmaf(w0.x, zv, pa[0]);  pa[1] = fmaf(w0.y, zv, pa[1]);
            pa[2] = fmaf(w0.z, zv, pa[2]);  pa[3] = fmaf(w0.w, zv, pa[3]);
            pa[4] = fmaf(w1.x, zv, pa[4]);  pa[5] = fmaf(w1.y, zv, pa[5]);
            pa[6] = fmaf(w1.z, zv, pa[6]);  pa[7] = fmaf(w1.w, zv, pa[7]);
            pa[8] = fmaf(w2.x, zv, pa[8]);  pa[9] = fmaf(w2.y, zv, pa[9]);
            pa[10] = fmaf(w2.z, zv, pa[10]); pa[11] = fmaf(w2.w, zv, pa[11]);
        }
        if (jj) {
            #pragma unroll
            for (int h = 0; h < 12; ++h) s_red[jj - 1][c][h] = pa[h];
        }
        __syncthreads();
        if (jj == 0) {
            #pragma unroll
            for (int h = 0; h < 12; ++h)
                g_buf[OFF_O + i * DO + h * 144 + 16 + c] =
                    pa[h] + s_red[0][c][h] + s_red[1][c][h];
        }
    }

    // scalar[h][c] = sum_j w[j][h] * v[j,h,c] — warp per head
    {
        const int h = t >> 5, lane = t & 31;
        const int cc = lane & 15, part = lane >> 4;
        float acc = 0.f;
        #pragma unroll 8
        for (int j = part; j < NR; j += 2)
            acc = fmaf(s_logit[j * 12 + h], g_buf[OFF_V + j * DQ + h * CH + cc], acc);
        acc += __shfl_down_sync(0xffffffffu, acc, 16);
        if (lane < 16) g_buf[OFF_O + i * DO + h * 144 + cc] = acc;
    }
}

// --------------------------------- layernorm over (s + c0 + c1), + coords
__global__ void __launch_bounds__(128) k_ln(const float* __restrict__ g,
                                            const float* __restrict__ b,
                                            const float* __restrict__ Wu,
                                            const float* __restrict__ bu,
                                            int fuse) {
    const int i = blockIdx.x, t = threadIdx.x, base = i * CS;

    float x0 = g_buf[OFF_S + base + t]       + g_buf[OFF_C + base + t]       + g_buf[OFF_C2 + base + t];
    float x1 = g_buf[OFF_S + base + t + 128] + g_buf[OFF_C + base + t + 128] + g_buf[OFF_C2 + base + t + 128];
    float x2 = g_buf[OFF_S + base + t + 256] + g_buf[OFF_C + base + t + 256] + g_buf[OFF_C2 + base + t + 256];

    float sum = x0 + x1 + x2;
    float sq  = x0 * x0 + x1 * x1 + x2 * x2;
    #pragma unroll
    for (int o = 16; o; o >>= 1) {
        sum += __shfl_xor_sync(0xffffffffu, sum, o);
        sq  += __shfl_xor_sync(0xffffffffu, sq, o);
    }
    __shared__ float sred[8];
    const int w = t >> 5, lane = t & 31;
    if (lane == 0) { sred[w] = sum; sred[4 + w] = sq; }
    __syncthreads();
    sum = sred[0] + sred[1] + sred[2] + sred[3];
    sq  = sred[4] + sred[5] + sred[6] + sred[7];
    float mu  = sum * (1.f / CS);
    float var = sq * (1.f / CS) - mu * mu;
    float rs  = rsqrtf(var + 1e-5f);

    float y0 = (x0 - mu) * rs * g[t]       + b[t];
    float y1 = (x1 - mu) * rs * g[t + 128] + b[t + 128];
    float y2 = (x2 - mu) * rs * g[t + 256] + b[t + 256];
    g_buf[OFF_S + base + t]       = y0;
    g_buf[OFF_S + base + t + 128] = y1;
    g_buf[OFF_S + base + t + 256] = y2;

    if (fuse) {
        float p0 = y0 * Wu[t * 6 + 0] + y1 * Wu[(t + 128) * 6 + 0] + y2 * Wu[(t + 256) * 6 + 0];
        float p1 = y0 * Wu[t * 6 + 1] + y1 * Wu[(t + 128) * 6 + 1] + y2 * Wu[(t + 256) * 6 + 1];
        float p2 = y0 * Wu[t * 6 + 2] + y1 * Wu[(t + 128) * 6 + 2] + y2 * Wu[(t + 256) * 6 + 2];
        #pragma unroll
        for (int o = 16; o; o >>= 1) {
            p0 += __shfl_xor_sync(0xffffffffu, p0, o);
            p1 += __shfl_xor_sync(0xffffffffu, p1, o);
            p2 += __shfl_xor_sync(0xffffffffu, p2, o);
        }
        __shared__ float sp[12];
        if (lane == 0) { sp[w] = p0; sp[4 + w] = p1; sp[8 + w] = p2; }
        __syncthreads();
        if (t == 0) {
            g_buf[OFF_CO + i * 3 + 0] += sp[0] + sp[1] + sp[2]  + sp[3]  + bu[0];
            g_buf[OFF_CO + i * 3 + 1] += sp[4] + sp[5] + sp[6]  + sp[7]  + bu[1];
            g_buf[OFF_CO + i * 3 + 2] += sp[8] + sp[9] + sp[10] + sp[11] + bu[2];
        }
    }
}

__global__ void k_out(float* __restrict__ out) {
    int i = blockIdx.x * blockDim.x + threadIdx.x;
    if (i < NR * 3) out[i] = g_buf[OFF_CO + i];
}

// ---------------------------------------------------------------- launch
extern "C" void kernel_launch(void* const* d_in, const int* in_sizes, int n_in,
                              void* d_out, int out_size) {
    const float* s   = (const float*)d_in[0];
    const float* z   = (const float*)d_in[1];
    const float* Wq  = (const float*)d_in[2];
    const float* bq  = (const float*)d_in[3];
    const float* Wk  = (const float*)d_in[4];
    const float* bk  = (const float*)d_in[5];
    const float* Wv  = (const float*)d_in[6];
    const float* bv  = (const float*)d_in[7];
    const float* Wb  = (const float*)d_in[8];
    const float* bb  = (const float*)d_in[9];
    const float* Wo  = (const float*)d_in[10];
    const float* bo  = (const float*)d_in[11];
    const float* Wt1 = (const float*)d_in[12];
    const float* bt1 = (const float*)d_in[13];
    const float* Wt2 = (const float*)d_in[14];
    const float* bt2 = (const float*)d_in[15];
    const float* Wu  = (const float*)d_in[16];
    const float* bu  = (const float*)d_in[17];
    const float* lng = (const float*)d_in[18];
    const float* lnb = (const float*)d_in[19];

    k_init<<<768, 256>>>(s);
    k_biaspre<<<dim3(1024, 2), 128>>>(z, Wb, bb);

    for (int r = 0; r < 2; ++r) {
        for (int l = 0; l < 8; ++l) {
            // qkv (3 weight sets, 3x16x3 = 144 blocks)
            k_gemm<0, 0><<<dim3(3, 16, 3), 128>>>(OFF_S,
                Wq + (size_t)l * CS * DQ, Wk + (size_t)l * CS * DQ, Wv + (size_t)l * CS * DQ,
                bq + l * DQ, bk + l * DQ, bv + l * DQ,
                OFF_Q, NR * DQ, CS, CS, DQ);
            k_attn<<<512, 384>>>(z, l);
            // Wo: K=1728, split-K=2 (partials summed in k_ln)
            k_gemm<0, 1><<<dim3(6, 16, 2), 128>>>(OFF_O,
                Wo + (size_t)l * DO * CS, nullptr, nullptr,
                bo + l * CS, nullptr, nullptr,
                OFF_C, OFF_C2 - OFF_C, DO, DO / 2, CS);
            k_ln<<<512, 128>>>(lng + (2 * l) * CS, lnb + (2 * l) * CS, nullptr, nullptr, 0);
            // FFN1: N=1536, ReLU
            k_gemm<1, 0><<<dim3(24, 16, 1), 128>>>(OFF_S,
                Wt1 + (size_t)l * CS * DF, nullptr, nullptr,
                bt1 + l * DF, nullptr, nullptr,
                OFF_T, 0, CS, CS, DF);
            // FFN2: K=1536, split-K=2
            k_gemm<0, 1><<<dim3(6, 16, 2), 128>>>(OFF_T,
                Wt2 + (size_t)l * DF * CS, nullptr, nullptr,
                bt2 + l * CS, nullptr, nullptr,
                OFF_C, OFF_C2 - OFF_C, DF, DF / 2, CS);
            k_ln<<<512, 128>>>(lng + (2 * l + 1) * CS, lnb + (2 * l + 1) * CS,
                               Wu + (size_t)l * CS * 6, bu + l * 6, 1);
        }
    }
    k_out<<<6, 256>>>((float*)d_out);
}

// round 5
// speedup vs baseline: 1.2281x; 1.1268x over previous
#include <cuda_runtime.h>
#include <cuda_fp16.h>
#include <math.h>

#define NR 512
#define CS 384
#define CZ 128
#define CH 16
#define NH 12
#define DQ 192
#define DO 1728
#define DF 1536

#define OFF_S  0
#define OFF_Q  196608
#define OFF_K  294912
#define OFF_V  393216
#define OFF_O  491520
#define OFF_T  1376256
#define OFF_C  2162688
#define OFF_C2 2359296
#define OFF_CO 2555904
#define OFF_B  2557440
#define BIAS_L 3145728
#define OFF_Z16 (OFF_B + 8L * BIAS_L)          /* 16.8M floats of half storage */

__device__ float g_buf[OFF_Z16 + (NR * NR * CZ) / 2];

// ------------------------------------------------------------------ init
__global__ void k_init(const float* __restrict__ s_in) {
    int i = blockIdx.x * blockDim.x + threadIdx.x;
    if (i < NR * CS) g_buf[OFF_S + i] = s_in[i];
    if (i < NR * 3)  g_buf[OFF_CO + i] = 0.f;
}

// ------------------------------------------------- z -> fp16 (one pass)
__global__ void k_z16(const float* __restrict__ z) {
    size_t idx = (size_t)blockIdx.x * 256 + threadIdx.x;   // 8.39M threads, 4 floats each
    float4 v = ((const float4*)z)[idx];
    __half2* dst = (__half2*)(g_buf + OFF_Z16);
    dst[idx * 2]     = __floats2half2_rn(v.x, v.y);
    dst[idx * 2 + 1] = __floats2half2_rn(v.z, v.w);
}

// ------------------------------------------- bias_z precompute, 8 layers
__global__ void __launch_bounds__(128) k_biaspre(const float* __restrict__ z,
                                                 const float* __restrict__ Wb,
                                                 const float* __restrict__ bb) {
    __shared__ float sWb[CZ * 48];
    __shared__ float sbb[48];
    __shared__ float sz[32][132];

    const int half = blockIdx.y;
    const int t = threadIdx.x;

    for (int idx = t; idx < CZ * 48; idx += 128) {
        int c = idx / 48, gh = idx - c * 48, g = gh / 12, hh = gh - g * 12;
        sWb[idx] = Wb[((half * 4 + g) * CZ + c) * NH + hh];
    }
    if (t < 48) sbb[t] = bb[half * 48 + t];

    const int rr = t >> 2, g = t & 3, l = half * 4 + g;
    const int r0 = blockIdx.x * 256;
    float* obase = g_buf + OFF_B + (size_t)l * BIAS_L;

    for (int chunk = 0; chunk < 256; chunk += 32) {
        __syncthreads();
        const float4* zsrc = (const float4*)(z + (size_t)(r0 + chunk) * CZ);
        for (int idx = t; idx < 32 * 32; idx += 128)
            *(float4*)&sz[idx >> 5][(idx & 31) * 4] = zsrc[idx];
        __syncthreads();

        float acc[12];
        #pragma unroll
        for (int hh = 0; hh < 12; ++hh) acc[hh] = sbb[g * 12 + hh];

        #pragma unroll 4
        for (int c = 0; c < CZ; ++c) {
            float zv = sz[rr][c];
            const float4* wp = (const float4*)(sWb + c * 48 + g * 12);
            float4 w0 = wp[0], w1 = wp[1], w2 = wp[2];
            acc[0] = fmaf(zv, w0.x, acc[0]);  acc[1] = fmaf(zv, w0.y, acc[1]);
            acc[2] = fmaf(zv, w0.z, acc[2]);  acc[3] = fmaf(zv, w0.w, acc[3]);
            acc[4] = fmaf(zv, w1.x, acc[4]);  acc[5] = fmaf(zv, w1.y, acc[5]);
            acc[6] = fmaf(zv, w1.z, acc[6]);  acc[7] = fmaf(zv, w1.w, acc[7]);
            acc[8] = fmaf(zv, w2.x, acc[8]);  acc[9] = fmaf(zv, w2.y, acc[9]);
            acc[10] = fmaf(zv, w2.z, acc[10]); acc[11] = fmaf(zv, w2.w, acc[11]);
        }
        float* op = obase + (size_t)(r0 + chunk + rr) * NH;
        *(float4*)(op + 0) = make_float4(acc[0], acc[1], acc[2], acc[3]);
        *(float4*)(op + 4) = make_float4(acc[4], acc[5], acc[6], acc[7]);
        *(float4*)(op + 8) = make_float4(acc[8], acc[9], acc[10], acc[11]);
    }
}

// --------------------------------------------------------- tiled GEMM
template <int RELU, int SPLITK>
__global__ void __launch_bounds__(128) k_gemm(
    int a_off,
    const float* __restrict__ W0, const float* __restrict__ W1, const float* __restrict__ W2,
    const float* __restrict__ b0, const float* __restrict__ b1, const float* __restrict__ b2,
    int c_off, int c_zstride, int Kfull, int Kpart, int N)
{
    const int zb = blockIdx.z;
    const float* W; const float* bias; int ashift;
    if (SPLITK) {
        W = W0 + (size_t)zb * Kpart * N;
        bias = (zb == 0) ? b0 : nullptr;
        ashift = zb * Kpart;
    } else {
        W = (zb == 1) ? W1 : (zb == 2) ? W2 : W0;
        bias = (zb == 1) ? b1 : (zb == 2) ? b2 : b0;
        ashift = 0;
    }
    float* C = g_buf + c_off + (size_t)zb * c_zstride;

    __shared__ float As[16][36];
    __shared__ float Bs[16][64];

    const int t = threadIdx.x;
    const int lm = t >> 2, lk = (t & 3) << 2;
    const int bk = t >> 3, bn8 = (t & 7) << 3;
    const int ty = t >> 4, tx = t & 15;

    const float* Ap = g_buf + a_off + (size_t)(blockIdx.y * 32 + lm) * Kfull + ashift + lk;
    const float* Wp = W + (size_t)bk * N + blockIdx.x * 64 + bn8;

    float acc[4][4] = {};

    for (int k0 = 0; k0 < Kpart; k0 += 16) {
        float4 av = *(const float4*)(Ap + k0);
        float4 w0v = *(const float4*)(Wp + (size_t)k0 * N);
        float4 w1v = *(const float4*)(Wp + (size_t)k0 * N + 4);
        As[lk + 0][lm] = av.x; As[lk + 1][lm] = av.y;
        As[lk + 2][lm] = av.z; As[lk + 3][lm] = av.w;
        *(float4*)&Bs[bk][bn8]     = w0v;
        *(float4*)&Bs[bk][bn8 + 4] = w1v;
        __syncthreads();

        #pragma unroll
        for (int kk = 0; kk < 16; ++kk) {
            float4 a = *(const float4*)&As[kk][ty * 4];
            float4 b = *(const float4*)&Bs[kk][tx * 4];
            acc[0][0] = fmaf(a.x, b.x, acc[0][0]); acc[0][1] = fmaf(a.x, b.y, acc[0][1]);
            acc[0][2] = fmaf(a.x, b.z, acc[0][2]); acc[0][3] = fmaf(a.x, b.w, acc[0][3]);
            acc[1][0] = fmaf(a.y, b.x, acc[1][0]); acc[1][1] = fmaf(a.y, b.y, acc[1][1]);
            acc[1][2] = fmaf(a.y, b.z, acc[1][2]); acc[1][3] = fmaf(a.y, b.w, acc[1][3]);
            acc[2][0] = fmaf(a.z, b.x, acc[2][0]); acc[2][1] = fmaf(a.z, b.y, acc[2][1]);
            acc[2][2] = fmaf(a.z, b.z, acc[2][2]); acc[2][3] = fmaf(a.z, b.w, acc[2][3]);
            acc[3][0] = fmaf(a.w, b.x, acc[3][0]); acc[3][1] = fmaf(a.w, b.y, acc[3][1]);
            acc[3][2] = fmaf(a.w, b.z, acc[3][2]); acc[3][3] = fmaf(a.w, b.w, acc[3][3]);
        }
        __syncthreads();
    }

    const int row = blockIdx.y * 32 + ty * 4;
    const int col = blockIdx.x * 64 + tx * 4;
    float4 bv = make_float4(0.f, 0.f, 0.f, 0.f);
    if (bias) bv = *(const float4*)(bias + col);
    #pragma unroll
    for (int mi = 0; mi < 4; ++mi) {
        float4 out;
        out.x = acc[mi][0] + bv.x; out.y = acc[mi][1] + bv.y;
        out.z = acc[mi][2] + bv.z; out.w = acc[mi][3] + bv.w;
        if (RELU) {
            out.x = fmaxf(out.x, 0.f); out.y = fmaxf(out.y, 0.f);
            out.z = fmaxf(out.z, 0.f); out.w = fmaxf(out.w, 0.f);
        }
        *(float4*)(C + (size_t)(row + mi) * N + col) = out;
    }
}

// --------------------------------------------------- fused attention row
__global__ void __launch_bounds__(384) k_attn(int l) {
    __shared__ float s_logit[NR * NH];   // 24 KB
    __shared__ uint4 s_zu[1024];         // 16 KB: fp16 z tile / reduction scratch
    __shared__ float s_ms[NR];
    __shared__ float s_q[DQ];

    const int i = blockIdx.x;
    const int t = threadIdx.x;

    if (t < DQ) s_q[t] = g_buf[OFF_Q + i * DQ + t];
    const float cx = g_buf[OFF_CO + i * 3 + 0];
    const float cy = g_buf[OFF_CO + i * 3 + 1];
    const float cz2 = g_buf[OFF_CO + i * 3 + 2];
    for (int j = t; j < NR; j += 384) {
        float dx = g_buf[OFF_CO + j * 3 + 0] - cx;
        float dy = g_buf[OFF_CO + j * 3 + 1] - cy;
        float dz = g_buf[OFF_CO + j * 3 + 2] - cz2;
        float sq = dx * dx + dy * dy + dz * dz;
        s_ms[j] = (sq <= 25.f) ? 1.f : ((sq <= 225.f) ? 0.3f : 0.05f);
    }
    __syncthreads();

    // logits = q.k/4 + bias_z + ms
    const float* bias = g_buf + OFF_B + (size_t)l * BIAS_L + (size_t)i * (NR * NH);
    #pragma unroll 4
    for (int idx = t; idx < NR * NH; idx += 384) {
        int j = idx / 12, h = idx - j * 12;
        const float* kp = g_buf + OFF_K + j * DQ + h * CH;
        const float4* qp = (const float4*)(s_q + h * CH);
        float4 k0 = *(const float4*)(kp + 0), k1 = *(const float4*)(kp + 4);
        float4 k2 = *(const float4*)(kp + 8), k3 = *(const float4*)(kp + 12);
        float4 q0 = qp[0], q1 = qp[1], q2 = qp[2], q3 = qp[3];
        float d = k0.x * q0.x;
        d = fmaf(k0.y, q0.y, d); d = fmaf(k0.z, q0.z, d); d = fmaf(k0.w, q0.w, d);
        d = fmaf(k1.x, q1.x, d); d = fmaf(k1.y, q1.y, d); d = fmaf(k1.z, q1.z, d); d = fmaf(k1.w, q1.w, d);
        d = fmaf(k2.x, q2.x, d); d = fmaf(k2.y, q2.y, d); d = fmaf(k2.z, q2.z, d); d = fmaf(k2.w, q2.w, d);
        d = fmaf(k3.x, q3.x, d); d = fmaf(k3.y, q3.y, d); d = fmaf(k3.z, q3.z, d); d = fmaf(k3.w, q3.w, d);
        s_logit[idx] = fmaf(d, 0.25f, bias[idx] + s_ms[j]);
    }
    __syncthreads();

    // softmax over j, warp per head
    {
        int h = t >> 5, lane = t & 31;
        float m = -1e30f;
        for (int j = lane; j < NR; j += 32) m = fmaxf(m, s_logit[j * 12 + h]);
        #pragma unroll
        for (int o = 16; o; o >>= 1) m = fmaxf(m, __shfl_xor_sync(0xffffffffu, m, o));
        float ssum = 0.f;
        for (int j = lane; j < NR; j += 32) {
            float e = __expf(s_logit[j * 12 + h] - m);
            s_logit[j * 12 + h] = e; ssum += e;
        }
        #pragma unroll
        for (int o = 16; o; o >>= 1) ssum += __shfl_xor_sync(0xffffffffu, ssum, o);
        float inv = 1.f / ssum;
        for (int j = lane; j < NR; j += 32) s_logit[j * 12 + h] *= inv;
    }

    // pair[h][c] = sum_j w[j][h] * z[i,j,c] — fp16 z staged in smem tiles
    {
        const int c = t & 127, jg = t >> 7;
        float pa[12] = {};
        const __half* z16 = (const __half*)(g_buf + OFF_Z16);
        const size_t zrow = (size_t)i * (NR * CZ);
        #pragma unroll 1
        for (int tile = 0; tile < 8; ++tile) {
            __syncthreads();
            const uint4* src = (const uint4*)(z16 + zrow + (size_t)tile * 64 * CZ);
            #pragma unroll
            for (int v2 = 0; v2 < 3; ++v2) {
                int v = t + v2 * 384;
                if (v < 1024) s_zu[v] = src[v];
            }
            __syncthreads();
            const __half* zt = (const __half*)s_zu;
            const float* wbase = s_logit + tile * 64 * 12;
            for (int lj = jg; lj < 64; lj += 3) {
                float zv = __half2float(zt[lj * CZ + c]);
                const float4* wr = (const float4*)(wbase + lj * 12);
                float4 w0 = wr[0], w1 = wr[1], w2 = wr[2];
                pa[0] = fmaf(w0.x, zv, pa[0]);  pa[1] = fmaf(w0.y, zv, pa[1]);
                pa[2] = fmaf(w0.z, zv, pa[2]);  pa[3] = fmaf(w0.w, zv, pa[3]);
                pa[4] = fmaf(w1.x, zv, pa[4]);  pa[5] = fmaf(w1.y, zv, pa[5]);
                pa[6] = fmaf(w1.z, zv, pa[6]);  pa[7] = fmaf(w1.w, zv, pa[7]);
                pa[8] = fmaf(w2.x, zv, pa[8]);  pa[9] = fmaf(w2.y, zv, pa[9]);
                pa[10] = fmaf(w2.z, zv, pa[10]); pa[11] = fmaf(w2.w, zv, pa[11]);
            }
        }
        __syncthreads();
        float* s_redf = (float*)s_zu;       // reuse tile buffer: 2*128*12*4B = 12KB
        if (jg) {
            #pragma unroll
            for (int h = 0; h < 12; ++h) s_redf[((jg - 1) * 128 + c) * 12 + h] = pa[h];
        }
        __syncthreads();
        if (jg == 0) {
            #pragma unroll
            for (int h = 0; h < 12; ++h)
                g_buf[OFF_O + i * DO + h * 144 + 16 + c] =
                    pa[h] + s_redf[c * 12 + h] + s_redf[(128 + c) * 12 + h];
        }
    }

    // scalar[h][c] = sum_j w[j][h] * v[j,h,c] — warp per head
    {
        const int h = t >> 5, lane = t & 31;
        const int cc = lane & 15, part = lane >> 4;
        float acc = 0.f;
        #pragma unroll 8
        for (int j = part; j < NR; j += 2)
            acc = fmaf(s_logit[j * 12 + h], g_buf[OFF_V + j * DQ + h * CH + cc], acc);
        acc += __shfl_down_sync(0xffffffffu, acc, 16);
        if (lane < 16) g_buf[OFF_O + i * DO + h * 144 + cc] = acc;
    }
}

// --------------------------------- layernorm over (s + c0 + c1), + coords
__global__ void __launch_bounds__(128) k_ln(const float* __restrict__ g,
                                            const float* __restrict__ b,
                                            const float* __restrict__ Wu,
                                            const float* __restrict__ bu,
                                            int fuse) {
    const int i = blockIdx.x, t = threadIdx.x, base = i * CS;

    float x0 = g_buf[OFF_S + base + t]       + g_buf[OFF_C + base + t]       + g_buf[OFF_C2 + base + t];
    float x1 = g_buf[OFF_S + base + t + 128] + g_buf[OFF_C + base + t + 128] + g_buf[OFF_C2 + base + t + 128];
    float x2 = g_buf[OFF_S + base + t + 256] + g_buf[OFF_C + base + t + 256] + g_buf[OFF_C2 + base + t + 256];

    float sum = x0 + x1 + x2;
    float sq  = x0 * x0 + x1 * x1 + x2 * x2;
    #pragma unroll
    for (int o = 16; o; o >>= 1) {
        sum += __shfl_xor_sync(0xffffffffu, sum, o);
        sq  += __shfl_xor_sync(0xffffffffu, sq, o);
    }
    __shared__ float sred[8];
    const int w = t >> 5, lane = t & 31;
    if (lane == 0) { sred[w] = sum; sred[4 + w] = sq; }
    __syncthreads();
    sum = sred[0] + sred[1] + sred[2] + sred[3];
    sq  = sred[4] + sred[5] + sred[6] + sred[7];
    float mu  = sum * (1.f / CS);
    float var = sq * (1.f / CS) - mu * mu;
    float rs  = rsqrtf(var + 1e-5f);

    float y0 = (x0 - mu) * rs * g[t]       + b[t];
    float y1 = (x1 - mu) * rs * g[t + 128] + b[t + 128];
    float y2 = (x2 - mu) * rs * g[t + 256] + b[t + 256];
    g_buf[OFF_S + base + t]       = y0;
    g_buf[OFF_S + base + t + 128] = y1;
    g_buf[OFF_S + base + t + 256] = y2;

    if (fuse) {
        float p0 = y0 * Wu[t * 6 + 0] + y1 * Wu[(t + 128) * 6 + 0] + y2 * Wu[(t + 256) * 6 + 0];
        float p1 = y0 * Wu[t * 6 + 1] + y1 * Wu[(t + 128) * 6 + 1] + y2 * Wu[(t + 256) * 6 + 1];
        float p2 = y0 * Wu[t * 6 + 2] + y1 * Wu[(t + 128) * 6 + 2] + y2 * Wu[(t + 256) * 6 + 2];
        #pragma unroll
        for (int o = 16; o; o >>= 1) {
            p0 += __shfl_xor_sync(0xffffffffu, p0, o);
            p1 += __shfl_xor_sync(0xffffffffu, p1, o);
            p2 += __shfl_xor_sync(0xffffffffu, p2, o);
        }
        __shared__ float sp[12];
        if (lane == 0) { sp[w] = p0; sp[4 + w] = p1; sp[8 + w] = p2; }
        __syncthreads();
        if (t == 0) {
            g_buf[OFF_CO + i * 3 + 0] += sp[0] + sp[1] + sp[2]  + sp[3]  + bu[0];
            g_buf[OFF_CO + i * 3 + 1] += sp[4] + sp[5] + sp[6]  + sp[7]  + bu[1];
            g_buf[OFF_CO + i * 3 + 2] += sp[8] + sp[9] + sp[10] + sp[11] + bu[2];
        }
    }
}

__global__ void k_out(float* __restrict__ out) {
    int i = blockIdx.x * blockDim.x + threadIdx.x;
    if (i < NR * 3) out[i] = g_buf[OFF_CO + i];
}

// ---------------------------------------------------------------- launch
extern "C" void kernel_launch(void* const* d_in, const int* in_sizes, int n_in,
                              void* d_out, int out_size) {
    const float* s   = (const float*)d_in[0];
    const float* z   = (const float*)d_in[1];
    const float* Wq  = (const float*)d_in[2];
    const float* bq  = (const float*)d_in[3];
    const float* Wk  = (const float*)d_in[4];
    const float* bk  = (const float*)d_in[5];
    const float* Wv  = (const float*)d_in[6];
    const float* bv  = (const float*)d_in[7];
    const float* Wb  = (const float*)d_in[8];
    const float* bb  = (const float*)d_in[9];
    const float* Wo  = (const float*)d_in[10];
    const float* bo  = (const float*)d_in[11];
    const float* Wt1 = (const float*)d_in[12];
    const float* bt1 = (const float*)d_in[13];
    const float* Wt2 = (const float*)d_in[14];
    const float* bt2 = (const float*)d_in[15];
    const float* Wu  = (const float*)d_in[16];
    const float* bu  = (const float*)d_in[17];
    const float* lng = (const float*)d_in[18];
    const float* lnb = (const float*)d_in[19];

    k_init<<<768, 256>>>(s);
    k_z16<<<32768, 256>>>(z);
    k_biaspre<<<dim3(1024, 2), 128>>>(z, Wb, bb);

    for (int r = 0; r < 2; ++r) {
        for (int l = 0; l < 8; ++l) {
            k_gemm<0, 0><<<dim3(3, 16, 3), 128>>>(OFF_S,
                Wq + (size_t)l * CS * DQ, Wk + (size_t)l * CS * DQ, Wv + (size_t)l * CS * DQ,
                bq + l * DQ, bk + l * DQ, bv + l * DQ,
                OFF_Q, NR * DQ, CS, CS, DQ);
            k_attn<<<512, 384>>>(l);
            k_gemm<0, 1><<<dim3(6, 16, 2), 128>>>(OFF_O,
                Wo + (size_t)l * DO * CS, nullptr, nullptr,
                bo + l * CS, nullptr, nullptr,
                OFF_C, OFF_C2 - OFF_C, DO, DO / 2, CS);
            k_ln<<<512, 128>>>(lng + (2 * l) * CS, lnb + (2 * l) * CS, nullptr, nullptr, 0);
            k_gemm<1, 0><<<dim3(24, 16, 1), 128>>>(OFF_S,
                Wt1 + (size_t)l * CS * DF, nullptr, nullptr,
                bt1 + l * DF, nullptr, nullptr,
                OFF_T, 0, CS, CS, DF);
            k_gemm<0, 1><<<dim3(6, 16, 2), 128>>>(OFF_T,
                Wt2 + (size_t)l * DF * CS, nullptr, nullptr,
                bt2 + l * CS, nullptr, nullptr,
                OFF_C, OFF_C2 - OFF_C, DF, DF / 2, CS);
            k_ln<<<512, 128>>>(lng + (2 * l + 1) * CS, lnb + (2 * l + 1) * CS,
                               Wu + (size_t)l * CS * 6, bu + l * 6, 1);
        }
    }
    k_out<<<6, 256>>>((float*)d_out);
}

// round 7
// speedup vs baseline: 1.4234x; 1.1590x over previous
#include <cuda_runtime.h>
#include <cuda_fp16.h>
#include <math.h>

#define NR 512
#define CS 384
#define CZ 128
#define CH 16
#define NH 12
#define DQ 192
#define DO 1728
#define DF 1536

#define OFF_S  0
#define OFF_Q  196608
#define OFF_K  294912
#define OFF_V  393216
#define OFF_O  491520
#define OFF_T  1376256
#define OFF_C  2162688
#define OFF_C2 2359296
#define OFF_C3 2555904
#define OFF_CO 2752512
#define OFF_B  2754048
#define BIAS_L 3145728
#define OFF_Z16 (OFF_B + 8L * BIAS_L)

__device__ float g_buf[OFF_Z16 + (NR * NR * CZ) / 2];

// ------------------------------------------------------------------ init
__global__ void k_init(const float* __restrict__ s_in) {
    int i = blockIdx.x * blockDim.x + threadIdx.x;
    if (i < NR * CS) g_buf[OFF_S + i] = s_in[i];
    if (i < NR * 3)  g_buf[OFF_CO + i] = 0.f;
}

// ------------------------------------------------- z -> fp16 (one pass)
__global__ void k_z16(const float* __restrict__ z) {
    size_t idx = (size_t)blockIdx.x * 256 + threadIdx.x;
    float4 v = ((const float4*)z)[idx];
    __half2* dst = (__half2*)(g_buf + OFF_Z16);
    dst[idx * 2]     = __floats2half2_rn(v.x, v.y);
    dst[idx * 2 + 1] = __floats2half2_rn(v.z, v.w);
}

// ------------------------------------------- bias_z precompute, 8 layers
__global__ void __launch_bounds__(128) k_biaspre(const float* __restrict__ z,
                                                 const float* __restrict__ Wb,
                                                 const float* __restrict__ bb) {
    __shared__ float sWb[CZ * 48];
    __shared__ float sbb[48];
    __shared__ float sz[32][132];

    const int half = blockIdx.y;
    const int t = threadIdx.x;

    for (int idx = t; idx < CZ * 48; idx += 128) {
        int c = idx / 48, gh = idx - c * 48, g = gh / 12, hh = gh - g * 12;
        sWb[idx] = Wb[((half * 4 + g) * CZ + c) * NH + hh];
    }
    if (t < 48) sbb[t] = bb[half * 48 + t];

    const int rr = t >> 2, g = t & 3, l = half * 4 + g;
    const int r0 = blockIdx.x * 256;
    float* obase = g_buf + OFF_B + (size_t)l * BIAS_L;

    for (int chunk = 0; chunk < 256; chunk += 32) {
        __syncthreads();
        const float4* zsrc = (const float4*)(z + (size_t)(r0 + chunk) * CZ);
        for (int idx = t; idx < 32 * 32; idx += 128)
            *(float4*)&sz[idx >> 5][(idx & 31) * 4] = zsrc[idx];
        __syncthreads();

        float acc[12];
        #pragma unroll
        for (int hh = 0; hh < 12; ++hh) acc[hh] = sbb[g * 12 + hh];

        #pragma unroll 4
        for (int c = 0; c < CZ; ++c) {
            float zv = sz[rr][c];
            const float4* wp = (const float4*)(sWb + c * 48 + g * 12);
            float4 w0 = wp[0], w1 = wp[1], w2 = wp[2];
            acc[0] = fmaf(zv, w0.x, acc[0]);  acc[1] = fmaf(zv, w0.y, acc[1]);
            acc[2] = fmaf(zv, w0.z, acc[2]);  acc[3] = fmaf(zv, w0.w, acc[3]);
            acc[4] = fmaf(zv, w1.x, acc[4]);  acc[5] = fmaf(zv, w1.y, acc[5]);
            acc[6] = fmaf(zv, w1.z, acc[6]);  acc[7] = fmaf(zv, w1.w, acc[7]);
            acc[8] = fmaf(zv, w2.x, acc[8]);  acc[9] = fmaf(zv, w2.y, acc[9]);
            acc[10] = fmaf(zv, w2.z, acc[10]); acc[11] = fmaf(zv, w2.w, acc[11]);
        }
        float* op = obase + (size_t)(r0 + chunk + rr) * NH;
        *(float4*)(op + 0) = make_float4(acc[0], acc[1], acc[2], acc[3]);
        *(float4*)(op + 4) = make_float4(acc[4], acc[5], acc[6], acc[7]);
        *(float4*)(op + 8) = make_float4(acc[8], acc[9], acc[10], acc[11]);
    }
}

// --------------------------------------------------------- tiled GEMM v2
// BM=32, BN=64, BK=16, 256 threads (8 warps), 2x4 micro, double-buffered.
template <int RELU, int SPLITK>
__global__ void __launch_bounds__(256) k_gemm(
    int a_off,
    const float* __restrict__ W0, const float* __restrict__ W1, const float* __restrict__ W2,
    const float* __restrict__ b0, const float* __restrict__ b1, const float* __restrict__ b2,
    int c_off, int c_zstride, int Kfull, int Kpart, int N)
{
    const int zb = blockIdx.z;
    const float* W; const float* bias; int ashift;
    if (SPLITK) {
        W = W0 + (size_t)zb * Kpart * N;
        bias = (zb == 0) ? b0 : nullptr;
        ashift = zb * Kpart;
    } else {
        W = (zb == 1) ? W1 : (zb == 2) ? W2 : W0;
        bias = (zb == 1) ? b1 : (zb == 2) ? b2 : b0;
        ashift = 0;
    }
    float* C = g_buf + c_off + (size_t)zb * c_zstride;

    __shared__ float As[2][16][34];   // [buf][k][m], pad keeps float2 8B-aligned
    __shared__ float Bs[2][16][64];

    const int t = threadIdx.x;
    const int lm = t >> 3, lk = (t & 7) << 1;        // A: row 0..31, k even
    const int bk = t >> 4, bn = (t & 15) << 2;       // B: k 0..15, 4 cols
    const int ty = t >> 4, tx = t & 15;              // compute: rows ty*2, cols tx*4

    const float* Ap = g_buf + a_off + (size_t)(blockIdx.y * 32 + lm) * Kfull + ashift + lk;
    const float* Wp = W + (size_t)bk * N + blockIdx.x * 64 + bn;

    float acc[2][4] = {};

    // preload tile 0
    {
        float2 a0 = *(const float2*)(Ap);
        float4 b0v = *(const float4*)(Wp);
        As[0][lk][lm] = a0.x; As[0][lk + 1][lm] = a0.y;
        *(float4*)&Bs[0][bk][bn] = b0v;
    }
    __syncthreads();

    int buf = 0;
    for (int k0 = 0; k0 < Kpart; k0 += 16) {
        float2 a_nx; float4 b_nx;
        const bool more = (k0 + 16) < Kpart;
        if (more) {
            a_nx = *(const float2*)(Ap + k0 + 16);
            b_nx = *(const float4*)(Wp + (size_t)(k0 + 16) * N);
        }

        #pragma unroll
        for (int kk = 0; kk < 16; ++kk) {
            float2 a = *(const float2*)&As[buf][kk][ty * 2];
            float4 b = *(const float4*)&Bs[buf][kk][tx * 4];
            acc[0][0] = fmaf(a.x, b.x, acc[0][0]); acc[0][1] = fmaf(a.x, b.y, acc[0][1]);
            acc[0][2] = fmaf(a.x, b.z, acc[0][2]); acc[0][3] = fmaf(a.x, b.w, acc[0][3]);
            acc[1][0] = fmaf(a.y, b.x, acc[1][0]); acc[1][1] = fmaf(a.y, b.y, acc[1][1]);
            acc[1][2] = fmaf(a.y, b.z, acc[1][2]); acc[1][3] = fmaf(a.y, b.w, acc[1][3]);
        }

        if (more) {
            As[buf ^ 1][lk][lm] = a_nx.x; As[buf ^ 1][lk + 1][lm] = a_nx.y;
            *(float4*)&Bs[buf ^ 1][bk][bn] = b_nx;
        }
        __syncthreads();
        buf ^= 1;
    }

    const int row = blockIdx.y * 32 + ty * 2;
    const int col = blockIdx.x * 64 + tx * 4;
    float4 bv = make_float4(0.f, 0.f, 0.f, 0.f);
    if (bias) bv = *(const float4*)(bias + col);
    #pragma unroll
    for (int mi = 0; mi < 2; ++mi) {
        float4 out;
        out.x = acc[mi][0] + bv.x; out.y = acc[mi][1] + bv.y;
        out.z = acc[mi][2] + bv.z; out.w = acc[mi][3] + bv.w;
        if (RELU) {
            out.x = fmaxf(out.x, 0.f); out.y = fmaxf(out.y, 0.f);
            out.z = fmaxf(out.z, 0.f); out.w = fmaxf(out.w, 0.f);
        }
        *(float4*)(C + (size_t)(row + mi) * N + col) = out;
    }
}

// --------------------------------------------------- fused attention row
__global__ void __launch_bounds__(384) k_attn(int l) {
    __shared__ float s_logit[NR * NH];   // 24 KB
    __shared__ uint4 s_zu[1024];         // 16 KB: fp16 z tile / reduction scratch
    __shared__ float s_ms[NR];
    __shared__ float s_q[DQ];

    const int i = blockIdx.x;
    const int t = threadIdx.x;

    if (t < DQ) s_q[t] = g_buf[OFF_Q + i * DQ + t];
    const float cx = g_buf[OFF_CO + i * 3 + 0];
    const float cy = g_buf[OFF_CO + i * 3 + 1];
    const float cz2 = g_buf[OFF_CO + i * 3 + 2];
    for (int j = t; j < NR; j += 384) {
        float dx = g_buf[OFF_CO + j * 3 + 0] - cx;
        float dy = g_buf[OFF_CO + j * 3 + 1] - cy;
        float dz = g_buf[OFF_CO + j * 3 + 2] - cz2;
        float sq = dx * dx + dy * dy + dz * dz;
        s_ms[j] = (sq <= 25.f) ? 1.f : ((sq <= 225.f) ? 0.3f : 0.05f);
    }
    __syncthreads();

    const float* bias = g_buf + OFF_B + (size_t)l * BIAS_L + (size_t)i * (NR * NH);
    #pragma unroll 4
    for (int idx = t; idx < NR * NH; idx += 384) {
        int j = idx / 12, h = idx - j * 12;
        const float* kp = g_buf + OFF_K + j * DQ + h * CH;
        const float4* qp = (const float4*)(s_q + h * CH);
        float4 k0 = *(const float4*)(kp + 0), k1 = *(const float4*)(kp + 4);
        float4 k2 = *(const float4*)(kp + 8), k3 = *(const float4*)(kp + 12);
        float4 q0 = qp[0], q1 = qp[1], q2 = qp[2], q3 = qp[3];
        float d = k0.x * q0.x;
        d = fmaf(k0.y, q0.y, d); d = fmaf(k0.z, q0.z, d); d = fmaf(k0.w, q0.w, d);
        d = fmaf(k1.x, q1.x, d); d = fmaf(k1.y, q1.y, d); d = fmaf(k1.z, q1.z, d); d = fmaf(k1.w, q1.w, d);
        d = fmaf(k2.x, q2.x, d); d = fmaf(k2.y, q2.y, d); d = fmaf(k2.z, q2.z, d); d = fmaf(k2.w, q2.w, d);
        d = fmaf(k3.x, q3.x, d); d = fmaf(k3.y, q3.y, d); d = fmaf(k3.z, q3.z, d); d = fmaf(k3.w, q3.w, d);
        s_logit[idx] = fmaf(d, 0.25f, bias[idx] + s_ms[j]);
    }
    __syncthreads();

    {
        int h = t >> 5, lane = t & 31;
        float m = -1e30f;
        for (int j = lane; j < NR; j += 32) m = fmaxf(m, s_logit[j * 12 + h]);
        #pragma unroll
        for (int o = 16; o; o >>= 1) m = fmaxf(m, __shfl_xor_sync(0xffffffffu, m, o));
        float ssum = 0.f;
        for (int j = lane; j < NR; j += 32) {
            float e = __expf(s_logit[j * 12 + h] - m);
            s_logit[j * 12 + h] = e; ssum += e;
        }
        #pragma unroll
        for (int o = 16; o; o >>= 1) ssum += __shfl_xor_sync(0xffffffffu, ssum, o);
        float inv = 1.f / ssum;
        for (int j = lane; j < NR; j += 32) s_logit[j * 12 + h] *= inv;
    }

    {
        const int c = t & 127, jg = t >> 7;
        float pa[12] = {};
        const __half* z16 = (const __half*)(g_buf + OFF_Z16);
        const size_t zrow = (size_t)i * (NR * CZ);
        #pragma unroll 1
        for (int tile = 0; tile < 8; ++tile) {
            __syncthreads();
            const uint4* src = (const uint4*)(z16 + zrow + (size_t)tile * 64 * CZ);
            #pragma unroll
            for (int v2 = 0; v2 < 3; ++v2) {
                int v = t + v2 * 384;
                if (v < 1024) s_zu[v] = src[v];
            }
            __syncthreads();
            const __half* zt = (const __half*)s_zu;
            const float* wbase = s_logit + tile * 64 * 12;
            for (int lj = jg; lj < 64; lj += 3) {
                float zv = __half2float(zt[lj * CZ + c]);
                const float4* wr = (const float4*)(wbase + lj * 12);
                float4 w0 = wr[0], w1 = wr[1], w2 = wr[2];
                pa[0] = fmaf(w0.x, zv, pa[0]);  pa[1] = fmaf(w0.y, zv, pa[1]);
                pa[2] = fmaf(w0.z, zv, pa[2]);  pa[3] = fmaf(w0.w, zv, pa[3]);
                pa[4] = fmaf(w1.x, zv, pa[4]);  pa[5] = fmaf(w1.y, zv, pa[5]);
                pa[6] = fmaf(w1.z, zv, pa[6]);  pa[7] = fmaf(w1.w, zv, pa[7]);
                pa[8] = fmaf(w2.x, zv, pa[8]);  pa[9] = fmaf(w2.y, zv, pa[9]);
                pa[10] = fmaf(w2.z, zv, pa[10]); pa[11] = fmaf(w2.w, zv, pa[11]);
            }
        }
        __syncthreads();
        float* s_redf = (float*)s_zu;
        if (jg) {
            #pragma unroll
            for (int h = 0; h < 12; ++h) s_redf[((jg - 1) * 128 + c) * 12 + h] = pa[h];
        }
        __syncthreads();
        if (jg == 0) {
            #pragma unroll
            for (int h = 0; h < 12; ++h)
                g_buf[OFF_O + i * DO + h * 144 + 16 + c] =
                    pa[h] + s_redf[c * 12 + h] + s_redf[(128 + c) * 12 + h];
        }
    }

    {
        const int h = t >> 5, lane = t & 31;
        const int cc = lane & 15, part = lane >> 4;
        float acc = 0.f;
        #pragma unroll 8
        for (int j = part; j < NR; j += 2)
            acc = fmaf(s_logit[j * 12 + h], g_buf[OFF_V + j * DQ + h * CH + cc], acc);
        acc += __shfl_down_sync(0xffffffffu, acc, 16);
        if (lane < 16) g_buf[OFF_O + i * DO + h * 144 + cc] = acc;
    }
}

// --------------------------- layernorm over (s + c0 + c1 + c2), + coords
__global__ void __launch_bounds__(128) k_ln(const float* __restrict__ g,
                                            const float* __restrict__ b,
                                            const float* __restrict__ Wu,
                                            const float* __restrict__ bu,
                                            int fuse) {
    const int i = blockIdx.x, t = threadIdx.x, base = i * CS;

    float x0 = g_buf[OFF_S + base + t]       + g_buf[OFF_C + base + t]
             + g_buf[OFF_C2 + base + t]      + g_buf[OFF_C3 + base + t];
    float x1 = g_buf[OFF_S + base + t + 128] + g_buf[OFF_C + base + t + 128]
             + g_buf[OFF_C2 + base + t + 128] + g_buf[OFF_C3 + base + t + 128];
    float x2 = g_buf[OFF_S + base + t + 256] + g_buf[OFF_C + base + t + 256]
             + g_buf[OFF_C2 + base + t + 256] + g_buf[OFF_C3 + base + t + 256];

    float sum = x0 + x1 + x2;
    float sq  = x0 * x0 + x1 * x1 + x2 * x2;
    #pragma unroll
    for (int o = 16; o; o >>= 1) {
        sum += __shfl_xor_sync(0xffffffffu, sum, o);
        sq  += __shfl_xor_sync(0xffffffffu, sq, o);
    }
    __shared__ float sred[8];
    const int w = t >> 5, lane = t & 31;
    if (lane == 0) { sred[w] = sum; sred[4 + w] = sq; }
    __syncthreads();
    sum = sred[0] + sred[1] + sred[2] + sred[3];
    sq  = sred[4] + sred[5] + sred[6] + sred[7];
    float mu  = sum * (1.f / CS);
    float var = sq * (1.f / CS) - mu * mu;
    float rs  = rsqrtf(var + 1e-5f);

    float y0 = (x0 - mu) * rs * g[t]       + b[t];
    float y1 = (x1 - mu) * rs * g[t + 128] + b[t + 128];
    float y2 = (x2 - mu) * rs * g[t + 256] + b[t + 256];
    g_buf[OFF_S + base + t]       = y0;
    g_buf[OFF_S + base + t + 128] = y1;
    g_buf[OFF_S + base + t + 256] = y2;

    if (fuse) {
        float p0 = y0 * Wu[t * 6 + 0] + y1 * Wu[(t + 128) * 6 + 0] + y2 * Wu[(t + 256) * 6 + 0];
        float p1 = y0 * Wu[t * 6 + 1] + y1 * Wu[(t + 128) * 6 + 1] + y2 * Wu[(t + 256) * 6 + 1];
        float p2 = y0 * Wu[t * 6 + 2] + y1 * Wu[(t + 128) * 6 + 2] + y2 * Wu[(t + 256) * 6 + 2];
        #pragma unroll
        for (int o = 16; o; o >>= 1) {
            p0 += __shfl_xor_sync(0xffffffffu, p0, o);
            p1 += __shfl_xor_sync(0xffffffffu, p1, o);
            p2 += __shfl_xor_sync(0xffffffffu, p2, o);
        }
        __shared__ float sp[12];
        if (lane == 0) { sp[w] = p0; sp[4 + w] = p1; sp[8 + w] = p2; }
        __syncthreads();
        if (t == 0) {
            g_buf[OFF_CO + i * 3 + 0] += sp[0] + sp[1] + sp[2]  + sp[3]  + bu[0];
            g_buf[OFF_CO + i * 3 + 1] += sp[4] + sp[5] + sp[6]  + sp[7]  + bu[1];
            g_buf[OFF_CO + i * 3 + 2] += sp[8] + sp[9] + sp[10] + sp[11] + bu[2];
        }
    }
}

// zero the split-K partial buffers C, C2, C3 (qkv path leaves them stale)
__global__ void k_zero3(int n) {
    int i = blockIdx.x * blockDim.x + threadIdx.x;
    if (i < n) {
        g_buf[OFF_C + i] = 0.f;
        g_buf[OFF_C2 + i] = 0.f;
        g_buf[OFF_C3 + i] = 0.f;
    }
}

__global__ void k_out(float* __restrict__ out) {
    int i = blockIdx.x * blockDim.x + threadIdx.x;
    if (i < NR * 3) out[i] = g_buf[OFF_CO + i];
}

// ---------------------------------------------------------------- launch
extern "C" void kernel_launch(void* const* d_in, const int* in_sizes, int n_in,
                              void* d_out, int out_size) {
    const float* s   = (const float*)d_in[0];
    const float* z   = (const float*)d_in[1];
    const float* Wq  = (const float*)d_in[2];
    const float* bq  = (const float*)d_in[3];
    const float* Wk  = (const float*)d_in[4];
    const float* bk  = (const float*)d_in[5];
    const float* Wv  = (const float*)d_in[6];
    const float* bv  = (const float*)d_in[7];
    const float* Wb  = (const float*)d_in[8];
    const float* bb  = (const float*)d_in[9];
    const float* Wo  = (const float*)d_in[10];
    const float* bo  = (const float*)d_in[11];
    const float* Wt1 = (const float*)d_in[12];
    const float* bt1 = (const float*)d_in[13];
    const float* Wt2 = (const float*)d_in[14];
    const float* bt2 = (const float*)d_in[15];
    const float* Wu  = (const float*)d_in[16];
    const float* bu  = (const float*)d_in[17];
    const float* lng = (const float*)d_in[18];
    const float* lnb = (const float*)d_in[19];

    k_init<<<768, 256>>>(s);
    k_z16<<<32768, 256>>>(z);
    k_biaspre<<<dim3(1024, 2), 128>>>(z, Wb, bb);

    for (int r = 0; r < 2; ++r) {
        for (int l = 0; l < 8; ++l) {
            // qkv: 3 weight sets
            k_gemm<0, 0><<<dim3(3, 16, 3), 256>>>(OFF_S,
                Wq + (size_t)l * CS * DQ, Wk + (size_t)l * CS * DQ, Wv + (size_t)l * CS * DQ,
                bq + l * DQ, bk + l * DQ, bv + l * DQ,
                OFF_Q, NR * DQ, CS, CS, DQ);
            k_attn<<<512, 384>>>(l);
            // Wo: K=1728, split-K=3
            k_gemm<0, 1><<<dim3(6, 16, 3), 256>>>(OFF_O,
                Wo + (size_t)l * DO * CS, nullptr, nullptr,
                bo + l * CS, nullptr, nullptr,
                OFF_C, OFF_C2 - OFF_C, DO, DO / 3, CS);
            k_ln<<<512, 128>>>(lng + (2 * l) * CS, lnb + (2 * l) * CS, nullptr, nullptr, 0);
            // FFN1: N=1536, ReLU
            k_gemm<1, 0><<<dim3(24, 16, 1), 256>>>(OFF_S,
                Wt1 + (size_t)l * CS * DF, nullptr, nullptr,
                bt1 + l * DF, nullptr, nullptr,
                OFF_T, 0, CS, CS, DF);
            // FFN2: K=1536, split-K=3
            k_gemm<0, 1><<<dim3(6, 16, 3), 256>>>(OFF_T,
                Wt2 + (size_t)l * DF * CS, nullptr, nullptr,
                bt2 + l * CS, nullptr, nullptr,
                OFF_C, OFF_C2 - OFF_C, DF, DF / 3, CS);
            k_ln<<<512, 128>>>(lng + (2 * l + 1) * CS, lnb + (2 * l + 1) * CS,
                               Wu + (size_t)l * CS * 6, bu + l * 6, 1);
        }
    }
    k_out<<<6, 256>>>((float*)d_out);
}

// round 12
// speedup vs baseline: 1.7022x; 1.1959x over previous
#include <cuda_runtime.h>
#include <cuda_fp16.h>
#include <cstdint>
#include <math.h>

#define NR 512
#define CS 384
#define CZ 128
#define CH 16
#define NH 12
#define DQ 192
#define DO 1728
#define DF 1536

#define OFF_S  0
#define OFF_Q  196608
#define OFF_K  294912
#define OFF_V  393216
#define OFF_O  491520
#define OFF_T  1376256
#define OFF_C  2162688
#define OFF_C2 2359296
#define OFF_C3 2555904
#define OFF_CO 2752512
#define OFF_B  2754048                 /* bias stored as fp16: 8 * 3145728 halves */
#define BIAS_LH 3145728                /* halves per layer */
#define OFF_Z16 15336960               /* OFF_B + 8*BIAS_LH/2 floats */
#define OFF_KV16 32114176              /* OFF_Z16 + NR*NR*CZ/2 */

__device__ float g_buf[32212480];

// ------------------------------------------------------ cp.async helpers
__device__ __forceinline__ void cp_async8(void* dst, const void* src) {
    unsigned int d = (unsigned int)__cvta_generic_to_shared(dst);
    asm volatile("cp.async.ca.shared.global [%0], [%1], 8;" :: "r"(d), "l"(src));
}
__device__ __forceinline__ void cp_async16(void* dst, const void* src) {
    unsigned int d = (unsigned int)__cvta_generic_to_shared(dst);
    asm volatile("cp.async.cg.shared.global [%0], [%1], 16;" :: "r"(d), "l"(src));
}
__device__ __forceinline__ void cp_commit() {
    asm volatile("cp.async.commit_group;" ::: "memory");
}
__device__ __forceinline__ void cp_wait2() {
    asm volatile("cp.async.wait_group 2;" ::: "memory");
}

// ------------------------------------------------------------------ init
__global__ void k_init(const float* __restrict__ s_in) {
    int i = blockIdx.x * blockDim.x + threadIdx.x;
    if (i < NR * CS) g_buf[OFF_S + i] = s_in[i];
    if (i < NR * 3)  g_buf[OFF_CO + i] = 0.f;
}

// ------------------------------------------------- z -> fp16 (one pass)
__global__ void k_z16(const float* __restrict__ z) {
    size_t idx = (size_t)blockIdx.x * 256 + threadIdx.x;
    float4 v = ((const float4*)z)[idx];
    __half2* dst = (__half2*)(g_buf + OFF_Z16);
    dst[idx * 2]     = __floats2half2_rn(v.x, v.y);
    dst[idx * 2 + 1] = __floats2half2_rn(v.z, v.w);
}

// ------------------------------------------- K,V -> fp16 (per iteration)
__global__ void k_kv16() {
    int i = blockIdx.x * 256 + threadIdx.x;      // 49152 threads, 2 elems each
    float2 kv = ((const float2*)(g_buf + OFF_K))[i];
    float2 vv = ((const float2*)(g_buf + OFF_V))[i];
    __half2* K2 = (__half2*)(g_buf + OFF_KV16);
    __half2* V2 = K2 + NR * DQ / 2;
    K2[i] = __floats2half2_rn(kv.x, kv.y);
    V2[i] = __floats2half2_rn(vv.x, vv.y);
}

// ------------------------------------------- bias_z precompute (fp16 out)
__global__ void __launch_bounds__(128) k_biaspre(const float* __restrict__ z,
                                                 const float* __restrict__ Wb,
                                                 const float* __restrict__ bb) {
    __shared__ float sWb[CZ * 48];
    __shared__ float sbb[48];
    __shared__ float sz[32][132];

    const int half_ = blockIdx.y;
    const int t = threadIdx.x;

    for (int idx = t; idx < CZ * 48; idx += 128) {
        int c = idx / 48, gh = idx - c * 48, g = gh / 12, hh = gh - g * 12;
        sWb[idx] = Wb[((half_ * 4 + g) * CZ + c) * NH + hh];
    }
    if (t < 48) sbb[t] = bb[half_ * 48 + t];

    const int rr = t >> 2, g = t & 3, l = half_ * 4 + g;
    const int r0 = blockIdx.x * 256;
    __half* obase = (__half*)(g_buf + OFF_B) + (size_t)l * BIAS_LH;

    for (int chunk = 0; chunk < 256; chunk += 32) {
        __syncthreads();
        const float4* zsrc = (const float4*)(z + (size_t)(r0 + chunk) * CZ);
        for (int idx = t; idx < 32 * 32; idx += 128)
            *(float4*)&sz[idx >> 5][(idx & 31) * 4] = zsrc[idx];
        __syncthreads();

        float acc[12];
        #pragma unroll
        for (int hh = 0; hh < 12; ++hh) acc[hh] = sbb[g * 12 + hh];

        #pragma unroll 4
        for (int c = 0; c < CZ; ++c) {
            float zv = sz[rr][c];
            const float4* wp = (const float4*)(sWb + c * 48 + g * 12);
            float4 w0 = wp[0], w1 = wp[1], w2 = wp[2];
            acc[0] = fmaf(zv, w0.x, acc[0]);  acc[1] = fmaf(zv, w0.y, acc[1]);
            acc[2] = fmaf(zv, w0.z, acc[2]);  acc[3] = fmaf(zv, w0.w, acc[3]);
            acc[4] = fmaf(zv, w1.x, acc[4]);  acc[5] = fmaf(zv, w1.y, acc[5]);
            acc[6] = fmaf(zv, w1.z, acc[6]);  acc[7] = fmaf(zv, w1.w, acc[7]);
            acc[8] = fmaf(zv, w2.x, acc[8]);  acc[9] = fmaf(zv, w2.y, acc[9]);
            acc[10] = fmaf(zv, w2.z, acc[10]); acc[11] = fmaf(zv, w2.w, acc[11]);
        }
        __half2* op = (__half2*)(obase + (size_t)(r0 + chunk + rr) * NH);
        op[0] = __floats2half2_rn(acc[0], acc[1]);
        op[1] = __floats2half2_rn(acc[2], acc[3]);
        op[2] = __floats2half2_rn(acc[4], acc[5]);
        op[3] = __floats2half2_rn(acc[6], acc[7]);
        op[4] = __floats2half2_rn(acc[8], acc[9]);
        op[5] = __floats2half2_rn(acc[10], acc[11]);
    }
}

// --------------------------------------------------------- GEMM v3
// BM=32, BN=64, BK=16, 256 threads, 2x4 micro, 4-stage cp.async pipeline.
template <int RELU, int SPLITK>
__global__ void __launch_bounds__(256) k_gemm(
    int a_off,
    const float* __restrict__ W0, const float* __restrict__ W1, const float* __restrict__ W2,
    const float* __restrict__ b0, const float* __restrict__ b1, const float* __restrict__ b2,
    int c_off, int c_zstride, int Kfull, int Kpart, int N)
{
    const int zb = blockIdx.z;
    const float* W; const float* bias; int ashift;
    if (SPLITK) {
        W = W0 + (size_t)zb * Kpart * N;
        bias = (zb == 0) ? b0 : nullptr;
        ashift = zb * Kpart;
    } else {
        W = (zb == 1) ? W1 : (zb == 2) ? W2 : W0;
        bias = (zb == 1) ? b1 : (zb == 2) ? b2 : b0;
        ashift = 0;
    }
    float* C = g_buf + c_off + (size_t)zb * c_zstride;

    __shared__ float As[4][32][16];   // [buf][m][k]
    __shared__ float Bs[4][16][64];   // [buf][k][n]

    const int t = threadIdx.x;
    const int lm = t >> 3, lk = (t & 7) << 1;        // A: row 0..31, 2 k's
    const int bk = t >> 4, bn = (t & 15) << 2;       // B: k 0..15, 4 cols
    const int ty = t >> 4, tx = t & 15;              // compute

    const float* Ap = g_buf + a_off + (size_t)(blockIdx.y * 32 + lm) * Kfull + ashift + lk;
    const float* Wp = W + (size_t)bk * N + blockIdx.x * 64 + bn;

    const int ntiles = Kpart >> 4;

    // prologue: issue tiles 0..2 into stages 0..2
    cp_async8(&As[0][lm][lk], Ap);
    cp_async16(&Bs[0][bk][bn], Wp);
    cp_commit();
    if (1 < ntiles) {
        cp_async8(&As[1][lm][lk], Ap + 16);
        cp_async16(&Bs[1][bk][bn], Wp + (size_t)16 * N);
    }
    cp_commit();
    if (2 < ntiles) {
        cp_async8(&As[2][lm][lk], Ap + 32);
        cp_async16(&Bs[2][bk][bn], Wp + (size_t)32 * N);
    }
    cp_commit();

    float acc[2][4] = {};

    for (int tl = 0; tl < ntiles; ++tl) {
        cp_wait2();
        __syncthreads();
        if (tl + 3 < ntiles) {
            int s = (tl + 3) & 3;
            cp_async8(&As[s][lm][lk], Ap + (tl + 3) * 16);
            cp_async16(&Bs[s][bk][bn], Wp + (size_t)(tl + 3) * 16 * N);
        }
        cp_commit();

        const int buf = tl & 3;
        #pragma unroll
        for (int kk = 0; kk < 16; ++kk) {
            float a0 = As[buf][ty * 2][kk];
            float a1 = As[buf][ty * 2 + 1][kk];
            float4 b = *(const float4*)&Bs[buf][kk][tx * 4];
            acc[0][0] = fmaf(a0, b.x, acc[0][0]); acc[0][1] = fmaf(a0, b.y, acc[0][1]);
            acc[0][2] = fmaf(a0, b.z, acc[0][2]); acc[0][3] = fmaf(a0, b.w, acc[0][3]);
            acc[1][0] = fmaf(a1, b.x, acc[1][0]); acc[1][1] = fmaf(a1, b.y, acc[1][1]);
            acc[1][2] = fmaf(a1, b.z, acc[1][2]); acc[1][3] = fmaf(a1, b.w, acc[1][3]);
        }
        __syncthreads();
    }

    const int row = blockIdx.y * 32 + ty * 2;
    const int col = blockIdx.x * 64 + tx * 4;
    float4 bv = make_float4(0.f, 0.f, 0.f, 0.f);
    if (bias) bv = *(const float4*)(bias + col);
    #pragma unroll
    for (int mi = 0; mi < 2; ++mi) {
        float4 out;
        out.x = acc[mi][0] + bv.x; out.y = acc[mi][1] + bv.y;
        out.z = acc[mi][2] + bv.z; out.w = acc[mi][3] + bv.w;
        if (RELU) {
            out.x = fmaxf(out.x, 0.f); out.y = fmaxf(out.y, 0.f);
            out.z = fmaxf(out.z, 0.f); out.w = fmaxf(out.w, 0.f);
        }
        *(float4*)(C + (size_t)(row + mi) * N + col) = out;
    }
}

// --------------------------------------------------- fused attention row
__global__ void __launch_bounds__(384) k_attn(int l) {
    __shared__ float s_logit[NR * NH];   // 24 KB
    __shared__ uint4 s_zu[1024];         // 16 KB: fp16 z tile / reduction scratch
    __shared__ float s_ms[NR];
    __shared__ float s_q[DQ];

    const int i = blockIdx.x;
    const int t = threadIdx.x;

    if (t < DQ) s_q[t] = g_buf[OFF_Q + i * DQ + t];
    const float cx = g_buf[OFF_CO + i * 3 + 0];
    const float cy = g_buf[OFF_CO + i * 3 + 1];
    const float cz2 = g_buf[OFF_CO + i * 3 + 2];
    for (int j = t; j < NR; j += 384) {
        float dx = g_buf[OFF_CO + j * 3 + 0] - cx;
        float dy = g_buf[OFF_CO + j * 3 + 1] - cy;
        float dz = g_buf[OFF_CO + j * 3 + 2] - cz2;
        float sq = dx * dx + dy * dy + dz * dz;
        s_ms[j] = (sq <= 25.f) ? 1.f : ((sq <= 225.f) ? 0.3f : 0.05f);
    }
    __syncthreads();

    const __half* K16 = (const __half*)(g_buf + OFF_KV16);
    const __half* V16 = K16 + NR * DQ;
    const __half* bias16 = (const __half*)(g_buf + OFF_B)
                           + (size_t)l * BIAS_LH + (size_t)i * (NR * NH);

    // logits = q.k/4 + bias_z + ms   (fp16 K, fp16 bias)
    #pragma unroll 4
    for (int idx = t; idx < NR * NH; idx += 384) {
        int j = idx / 12, h = idx - j * 12;
        const uint4* kp = (const uint4*)(K16 + j * DQ + h * CH);
        uint4 ka = kp[0], kb = kp[1];
        const __half2* k2a = (const __half2*)&ka;
        const __half2* k2b = (const __half2*)&kb;
        const float2* qp = (const float2*)(s_q + h * CH);
        float d = 0.f;
        #pragma unroll
        for (int u = 0; u < 4; ++u) {
            float2 kf = __half22float2(k2a[u]);
            float2 qf = qp[u];
            d = fmaf(kf.x, qf.x, d); d = fmaf(kf.y, qf.y, d);
        }
        #pragma unroll
        for (int u = 0; u < 4; ++u) {
            float2 kf = __half22float2(k2b[u]);
            float2 qf = qp[4 + u];
            d = fmaf(kf.x, qf.x, d); d = fmaf(kf.y, qf.y, d);
        }
        s_logit[idx] = fmaf(d, 0.25f, __half2float(bias16[idx]) + s_ms[j]);
    }
    __syncthreads();

    // softmax over j, warp per head
    {
        int h = t >> 5, lane = t & 31;
        float m = -1e30f;
        for (int j = lane; j < NR; j += 32) m = fmaxf(m, s_logit[j * 12 + h]);
        #pragma unroll
        for (int o = 16; o; o >>= 1) m = fmaxf(m, __shfl_xor_sync(0xffffffffu, m, o));
        float ssum = 0.f;
        for (int j = lane; j < NR; j += 32) {
            float e = __expf(s_logit[j * 12 + h] - m);
            s_logit[j * 12 + h] = e; ssum += e;
        }
        #pragma unroll
        for (int o = 16; o; o >>= 1) ssum += __shfl_xor_sync(0xffffffffu, ssum, o);
        float inv = 1.f / ssum;
        for (int j = lane; j < NR; j += 32) s_logit[j * 12 + h] *= inv;
    }

    // pair[h][c] = sum_j w[j][h] * z[i,j,c] — fp16 z staged in smem tiles
    {
        const int c = t & 127, jg = t >> 7;
        float pa[12] = {};
        const __half* z16 = (const __half*)(g_buf + OFF_Z16);
        const size_t zrow = (size_t)i * (NR * CZ);
        #pragma unroll 1
        for (int tile = 0; tile < 8; ++tile) {
            __syncthreads();
            const uint4* src = (const uint4*)(z16 + zrow + (size_t)tile * 64 * CZ);
            #pragma unroll
            for (int v2 = 0; v2 < 3; ++v2) {
                int v = t + v2 * 384;
                if (v < 1024) s_zu[v] = src[v];
            }
            __syncthreads();
            const __half* zt = (const __half*)s_zu;
            const float* wbase = s_logit + tile * 64 * 12;
            for (int lj = jg; lj < 64; lj += 3) {
                float zv = __half2float(zt[lj * CZ + c]);
                const float4* wr = (const float4*)(wbase + lj * 12);
                float4 w0 = wr[0], w1 = wr[1], w2 = wr[2];
                pa[0] = fmaf(w0.x, zv, pa[0]);  pa[1] = fmaf(w0.y, zv, pa[1]);
                pa[2] = fmaf(w0.z, zv, pa[2]);  pa[3] = fmaf(w0.w, zv, pa[3]);
                pa[4] = fmaf(w1.x, zv, pa[4]);  pa[5] = fmaf(w1.y, zv, pa[5]);
                pa[6] = fmaf(w1.z, zv, pa[6]);  pa[7] = fmaf(w1.w, zv, pa[7]);
                pa[8] = fmaf(w2.x, zv, pa[8]);  pa[9] = fmaf(w2.y, zv, pa[9]);
                pa[10] = fmaf(w2.z, zv, pa[10]); pa[11] = fmaf(w2.w, zv, pa[11]);
            }
        }
        __syncthreads();
        float* s_redf = (float*)s_zu;
        if (jg) {
            #pragma unroll
            for (int h = 0; h < 12; ++h) s_redf[((jg - 1) * 128 + c) * 12 + h] = pa[h];
        }
        __syncthreads();
        if (jg == 0) {
            #pragma unroll
            for (int h = 0; h < 12; ++h)
                g_buf[OFF_O + i * DO + h * 144 + 16 + c] =
                    pa[h] + s_redf[c * 12 + h] + s_redf[(128 + c) * 12 + h];
        }
    }

    // scalar[h][c] = sum_j w[j][h] * v[j,h,c] — fp16 V, warp per head
    {
        const int h = t >> 5, lane = t & 31;
        const int part = lane >> 3, c2 = lane & 7;
        const __half2* vp = (const __half2*)(V16 + h * CH) + c2;
        float2 acc2 = make_float2(0.f, 0.f);
        #pragma unroll 8
        for (int j = part; j < NR; j += 4) {
            float w = s_logit[j * 12 + h];
            float2 vf = __half22float2(vp[j * (DQ / 2)]);
            acc2.x = fmaf(w, vf.x, acc2.x);
            acc2.y = fmaf(w, vf.y, acc2.y);
        }
        acc2.x += __shfl_xor_sync(0xffffffffu, acc2.x, 8);
        acc2.y += __shfl_xor_sync(0xffffffffu, acc2.y, 8);
        acc2.x += __shfl_xor_sync(0xffffffffu, acc2.x, 16);
        acc2.y += __shfl_xor_sync(0xffffffffu, acc2.y, 16);
        if (lane < 8) *(float2*)(g_buf + OFF_O + i * DO + h * 144 + c2 * 2) = acc2;
    }
}

// --------------------------- layernorm over (s + c0 + c1 + c2), + coords
__global__ void __launch_bounds__(128) k_ln(const float* __restrict__ g,
                                            const float* __restrict__ b,
                                            const float* __restrict__ Wu,
                                            const float* __restrict__ bu,
                                            int fuse) {
    const int i = blockIdx.x, t = threadIdx.x, base = i * CS;

    float x0 = g_buf[OFF_S + base + t]       + g_buf[OFF_C + base + t]
             + g_buf[OFF_C2 + base + t]      + g_buf[OFF_C3 + base + t];
    float x1 = g_buf[OFF_S + base + t + 128] + g_buf[OFF_C + base + t + 128]
             + g_buf[OFF_C2 + base + t + 128] + g_buf[OFF_C3 + base + t + 128];
    float x2 = g_buf[OFF_S + base + t + 256] + g_buf[OFF_C + base + t + 256]
             + g_buf[OFF_C2 + base + t + 256] + g_buf[OFF_C3 + base + t + 256];

    float sum = x0 + x1 + x2;
    float sq  = x0 * x0 + x1 * x1 + x2 * x2;
    #pragma unroll
    for (int o = 16; o; o >>= 1) {
        sum += __shfl_xor_sync(0xffffffffu, sum, o);
        sq  += __shfl_xor_sync(0xffffffffu, sq, o);
    }
    __shared__ float sred[8];
    const int w = t >> 5, lane = t & 31;
    if (lane == 0) { sred[w] = sum; sred[4 + w] = sq; }
    __syncthreads();
    sum = sred[0] + sred[1] + sred[2] + sred[3];
    sq  = sred[4] + sred[5] + sred[6] + sred[7];
    float mu  = sum * (1.f / CS);
    float var = sq * (1.f / CS) - mu * mu;
    float rs  = rsqrtf(var + 1e-5f);

    float y0 = (x0 - mu) * rs * g[t]       + b[t];
    float y1 = (x1 - mu) * rs * g[t + 128] + b[t + 128];
    float y2 = (x2 - mu) * rs * g[t + 256] + b[t + 256];
    g_buf[OFF_S + base + t]       = y0;
    g_buf[OFF_S + base + t + 128] = y1;
    g_buf[OFF_S + base + t + 256] = y2;

    if (fuse) {
        float p0 = y0 * Wu[t * 6 + 0] + y1 * Wu[(t + 128) * 6 + 0] + y2 * Wu[(t + 256) * 6 + 0];
        float p1 = y0 * Wu[t * 6 + 1] + y1 * Wu[(t + 128) * 6 + 1] + y2 * Wu[(t + 256) * 6 + 1];
        float p2 = y0 * Wu[t * 6 + 2] + y1 * Wu[(t + 128) * 6 + 2] + y2 * Wu[(t + 256) * 6 + 2];
        #pragma unroll
        for (int o = 16; o; o >>= 1) {
            p0 += __shfl_xor_sync(0xffffffffu, p0, o);
            p1 += __shfl_xor_sync(0xffffffffu, p1, o);
            p2 += __shfl_xor_sync(0xffffffffu, p2, o);
        }
        __shared__ float sp[12];
        if (lane == 0) { sp[w] = p0; sp[4 + w] = p1; sp[8 + w] = p2; }
        __syncthreads();
        if (t == 0) {
            g_buf[OFF_CO + i * 3 + 0] += sp[0] + sp[1] + sp[2]  + sp[3]  + bu[0];
            g_buf[OFF_CO + i * 3 + 1] += sp[4] + sp[5] + sp[6]  + sp[7]  + bu[1];
            g_buf[OFF_CO + i * 3 + 2] += sp[8] + sp[9] + sp[10] + sp[11] + bu[2];
        }
    }
}

__global__ void k_out(float* __restrict__ out) {
    int i = blockIdx.x * blockDim.x + threadIdx.x;
    if (i < NR * 3) out[i] = g_buf[OFF_CO + i];
}

// ---------------------------------------------------------------- launch
extern "C" void kernel_launch(void* const* d_in, const int* in_sizes, int n_in,
                              void* d_out, int out_size) {
    const float* s   = (const float*)d_in[0];
    const float* z   = (const float*)d_in[1];
    const float* Wq  = (const float*)d_in[2];
    const float* bq  = (const float*)d_in[3];
    const float* Wk  = (const float*)d_in[4];
    const float* bk  = (const float*)d_in[5];
    const float* Wv  = (const float*)d_in[6];
    const float* bv  = (const float*)d_in[7];
    const float* Wb  = (const float*)d_in[8];
    const float* bb  = (const float*)d_in[9];
    const float* Wo  = (const float*)d_in[10];
    const float* bo  = (const float*)d_in[11];
    const float* Wt1 = (const float*)d_in[12];
    const float* bt1 = (const float*)d_in[13];
    const float* Wt2 = (const float*)d_in[14];
    const float* bt2 = (const float*)d_in[15];
    const float* Wu  = (const float*)d_in[16];
    const float* bu  = (const float*)d_in[17];
    const float* lng = (const float*)d_in[18];
    const float* lnb = (const float*)d_in[19];

    k_init<<<768, 256>>>(s);
    k_z16<<<32768, 256>>>(z);
    k_biaspre<<<dim3(1024, 2), 128>>>(z, Wb, bb);

    for (int r = 0; r < 2; ++r) {
        for (int l = 0; l < 8; ++l) {
            // qkv: 3 weight sets
            k_gemm<0, 0><<<dim3(3, 16, 3), 256>>>(OFF_S,
                Wq + (size_t)l * CS * DQ, Wk + (size_t)l * CS * DQ, Wv + (size_t)l * CS * DQ,
                bq + l * DQ, bk + l * DQ, bv + l * DQ,
                OFF_Q, NR * DQ, CS, CS, DQ);
            k_kv16<<<192, 256>>>();
            k_attn<<<512, 384>>>(l);
            // Wo: K=1728, split-K=3
            k_gemm<0, 1><<<dim3(6, 16, 3), 256>>>(OFF_O,
                Wo + (size_t)l * DO * CS, nullptr, nullptr,
                bo + l * CS, nullptr, nullptr,
                OFF_C, OFF_C2 - OFF_C, DO, DO / 3, CS);
            k_ln<<<512, 128>>>(lng + (2 * l) * CS, lnb + (2 * l) * CS, nullptr, nullptr, 0);
            // FFN1: N=1536, ReLU
            k_gemm<1, 0><<<dim3(24, 16, 1), 256>>>(OFF_S,
                Wt1 + (size_t)l * CS * DF, nullptr, nullptr,
                bt1 + l * DF, nullptr, nullptr,
                OFF_T, 0, CS, CS, DF);
            // FFN2: K=1536, split-K=3
            k_gemm<0, 1><<<dim3(6, 16, 3), 256>>>(OFF_T,
                Wt2 + (size_t)l * DF * CS, nullptr, nullptr,
                bt2 + l * CS, nullptr, nullptr,
                OFF_C, OFF_C2 - OFF_C, DF, DF / 3, CS);
            k_ln<<<512, 128>>>(lng + (2 * l + 1) * CS, lnb + (2 * l + 1) * CS,
                               Wu + (size_t)l * CS * 6, bu + l * 6, 1);
        }
    }
    k_out<<<6, 256>>>((float*)d_out);
}

// round 17
// speedup vs baseline: 2.0847x; 1.2247x over previous
#include <cuda_runtime.h>
#include <cuda_fp16.h>
#include <cstdint>
#include <math.h>

#define NR 512
#define CS 384
#define CZ 128
#define CH 16
#define NH 12
#define DQ 192
#define DO 1728
#define DF 1536

#define OFF_S  0
#define OFF_Q  196608
#define OFF_K  294912
#define OFF_V  393216
#define OFF_O  491520
#define OFF_T  1376256
#define OFF_C  2162688
#define OFF_C2 2359296
#define OFF_C3 2555904
#define OFF_CO 2752512
#define OFF_B  2754048                 /* bias stored as fp16: 8 * 3145728 halves */
#define BIAS_LH 3145728                /* halves per layer */
#define OFF_Z16 15336960               /* OFF_B + 8*BIAS_LH/2 floats */
#define OFF_KV16 32114176              /* OFF_Z16 + NR*NR*CZ/2 */

__device__ float g_buf[32212480];

// ------------------------------------------------------ cp.async helpers
__device__ __forceinline__ void cp_async8(void* dst, const void* src) {
    unsigned int d = (unsigned int)__cvta_generic_to_shared(dst);
    asm volatile("cp.async.ca.shared.global [%0], [%1], 8;" :: "r"(d), "l"(src));
}
__device__ __forceinline__ void cp_async16(void* dst, const void* src) {
    unsigned int d = (unsigned int)__cvta_generic_to_shared(dst);
    asm volatile("cp.async.cg.shared.global [%0], [%1], 16;" :: "r"(d), "l"(src));
}
__device__ __forceinline__ void cp_commit() {
    asm volatile("cp.async.commit_group;" ::: "memory");
}
__device__ __forceinline__ void cp_wait2() {
    asm volatile("cp.async.wait_group 2;" ::: "memory");
}

// ------------------------------------------------------ tf32 mma helpers
__device__ __forceinline__ unsigned int f2tf(float x) {
    unsigned int r;
    asm("cvt.rna.tf32.f32 %0, %1;" : "=r"(r) : "f"(x));
    return r;
}
__device__ __forceinline__ void mma_tf32(float* c,
    unsigned int a0, unsigned int a1, unsigned int a2, unsigned int a3,
    unsigned int b0, unsigned int b1)
{
    asm volatile(
        "mma.sync.aligned.m16n8k8.row.col.f32.tf32.tf32.f32 "
        "{%0,%1,%2,%3}, {%4,%5,%6,%7}, {%8,%9}, {%0,%1,%2,%3};"
        : "+f"(c[0]), "+f"(c[1]), "+f"(c[2]), "+f"(c[3])
        : "r"(a0), "r"(a1), "r"(a2), "r"(a3), "r"(b0), "r"(b1));
}

// ------------------------------------------------------------------ init
__global__ void k_init(const float* __restrict__ s_in) {
    int i = blockIdx.x * blockDim.x + threadIdx.x;
    if (i < NR * CS) g_buf[OFF_S + i] = s_in[i];
    if (i < NR * 3)  g_buf[OFF_CO + i] = 0.f;
}

// ------------------------------------------------- z -> fp16 (one pass)
__global__ void k_z16(const float* __restrict__ z) {
    size_t idx = (size_t)blockIdx.x * 256 + threadIdx.x;
    float4 v = ((const float4*)z)[idx];
    __half2* dst = (__half2*)(g_buf + OFF_Z16);
    dst[idx * 2]     = __floats2half2_rn(v.x, v.y);
    dst[idx * 2 + 1] = __floats2half2_rn(v.z, v.w);
}

// ------------------------------------------- K,V -> fp16 (per iteration)
__global__ void k_kv16() {
    int i = blockIdx.x * 256 + threadIdx.x;
    float2 kv = ((const float2*)(g_buf + OFF_K))[i];
    float2 vv = ((const float2*)(g_buf + OFF_V))[i];
    __half2* K2 = (__half2*)(g_buf + OFF_KV16);
    __half2* V2 = K2 + NR * DQ / 2;
    K2[i] = __floats2half2_rn(kv.x, kv.y);
    V2[i] = __floats2half2_rn(vv.x, vv.y);
}

// ------------------------------------------- bias_z precompute (fp16 out)
__global__ void __launch_bounds__(128) k_biaspre(const float* __restrict__ z,
                                                 const float* __restrict__ Wb,
                                                 const float* __restrict__ bb) {
    __shared__ float sWb[CZ * 48];
    __shared__ float sbb[48];
    __shared__ float sz[32][132];

    const int half_ = blockIdx.y;
    const int t = threadIdx.x;

    for (int idx = t; idx < CZ * 48; idx += 128) {
        int c = idx / 48, gh = idx - c * 48, g = gh / 12, hh = gh - g * 12;
        sWb[idx] = Wb[((half_ * 4 + g) * CZ + c) * NH + hh];
    }
    if (t < 48) sbb[t] = bb[half_ * 48 + t];

    const int rr = t >> 2, g = t & 3, l = half_ * 4 + g;
    const int r0 = blockIdx.x * 256;
    __half* obase = (__half*)(g_buf + OFF_B) + (size_t)l * BIAS_LH;

    for (int chunk = 0; chunk < 256; chunk += 32) {
        __syncthreads();
        const float4* zsrc = (const float4*)(z + (size_t)(r0 + chunk) * CZ);
        for (int idx = t; idx < 32 * 32; idx += 128)
            *(float4*)&sz[idx >> 5][(idx & 31) * 4] = zsrc[idx];
        __syncthreads();

        float acc[12];
        #pragma unroll
        for (int hh = 0; hh < 12; ++hh) acc[hh] = sbb[g * 12 + hh];

        #pragma unroll 4
        for (int c = 0; c < CZ; ++c) {
            float zv = sz[rr][c];
            const float4* wp = (const float4*)(sWb + c * 48 + g * 12);
            float4 w0 = wp[0], w1 = wp[1], w2 = wp[2];
            acc[0] = fmaf(zv, w0.x, acc[0]);  acc[1] = fmaf(zv, w0.y, acc[1]);
            acc[2] = fmaf(zv, w0.z, acc[2]);  acc[3] = fmaf(zv, w0.w, acc[3]);
            acc[4] = fmaf(zv, w1.x, acc[4]);  acc[5] = fmaf(zv, w1.y, acc[5]);
            acc[6] = fmaf(zv, w1.z, acc[6]);  acc[7] = fmaf(zv, w1.w, acc[7]);
            acc[8] = fmaf(zv, w2.x, acc[8]);  acc[9] = fmaf(zv, w2.y, acc[9]);
            acc[10] = fmaf(zv, w2.z, acc[10]); acc[11] = fmaf(zv, w2.w, acc[11]);
        }
        __half2* op = (__half2*)(obase + (size_t)(r0 + chunk + rr) * NH);
        op[0] = __floats2half2_rn(acc[0], acc[1]);
        op[1] = __floats2half2_rn(acc[2], acc[3]);
        op[2] = __floats2half2_rn(acc[4], acc[5]);
        op[3] = __floats2half2_rn(acc[6], acc[7]);
        op[4] = __floats2half2_rn(acc[8], acc[9]);
        op[5] = __floats2half2_rn(acc[10], acc[11]);
    }
}

// --------------------------------------------------------- GEMM v4 (tf32 MMA)
// BM=32, BN=64, BK=16, 256 threads (8 warps), 4-stage cp.async pipeline.
// Warp w computes a 16x16 C tile: m_base=(w&1)*16, n_base=(w>>1)*16.
template <int RELU, int SPLITK>
__global__ void __launch_bounds__(256) k_gemm(
    int a_off,
    const float* __restrict__ W0, const float* __restrict__ W1, const float* __restrict__ W2,
    const float* __restrict__ b0, const float* __restrict__ b1, const float* __restrict__ b2,
    int c_off, int c_zstride, int Kfull, int Kpart, int N)
{
    const int zb = blockIdx.z;
    const float* W; const float* bias; int ashift;
    if (SPLITK) {
        W = W0 + (size_t)zb * Kpart * N;
        bias = (zb == 0) ? b0 : nullptr;
        ashift = zb * Kpart;
    } else {
        W = (zb == 1) ? W1 : (zb == 2) ? W2 : W0;
        bias = (zb == 1) ? b1 : (zb == 2) ? b2 : b0;
        ashift = 0;
    }
    float* C = g_buf + c_off + (size_t)zb * c_zstride;

    __shared__ float As[4][32][18];   // [buf][m][k], pad 18: conflict-free frags
    __shared__ float Bs[4][16][68];   // [buf][k][n], pad 68

    const int t = threadIdx.x;
    const int lm = t >> 3, lk = (t & 7) << 1;        // A load: row 0..31, 2 k's
    const int bk = t >> 4, bn = (t & 15) << 2;       // B load: k 0..15, 4 cols

    const int w = t >> 5, lane = t & 31;
    const int gid = lane >> 2, tig = lane & 3;       // mma fragment coords
    const int m_base = (w & 1) * 16;
    const int n_base = (w >> 1) * 16;

    const float* Ap = g_buf + a_off + (size_t)(blockIdx.y * 32 + lm) * Kfull + ashift + lk;
    const float* Wp = W + (size_t)bk * N + blockIdx.x * 64 + bn;

    const int ntiles = Kpart >> 4;

    // prologue: tiles 0..2 into stages 0..2
    cp_async8(&As[0][lm][lk], Ap);
    cp_async16(&Bs[0][bk][bn], Wp);
    cp_commit();
    if (1 < ntiles) {
        cp_async8(&As[1][lm][lk], Ap + 16);
        cp_async16(&Bs[1][bk][bn], Wp + (size_t)16 * N);
    }
    cp_commit();
    if (2 < ntiles) {
        cp_async8(&As[2][lm][lk], Ap + 32);
        cp_async16(&Bs[2][bk][bn], Wp + (size_t)32 * N);
    }
    cp_commit();

    float acc0[4] = {0.f, 0.f, 0.f, 0.f};
    float acc1[4] = {0.f, 0.f, 0.f, 0.f};

    for (int tl = 0; tl < ntiles; ++tl) {
        cp_wait2();
        __syncthreads();
        if (tl + 3 < ntiles) {
            int s = (tl + 3) & 3;
            cp_async8(&As[s][lm][lk], Ap + (tl + 3) * 16);
            cp_async16(&Bs[s][bk][bn], Wp + (size_t)(tl + 3) * 16 * N);
        }
        cp_commit();

        const int buf = tl & 3;
        #pragma unroll
        for (int ks = 0; ks < 16; ks += 8) {
            unsigned int a0 = f2tf(As[buf][m_base + gid][ks + tig]);
            unsigned int a1 = f2tf(As[buf][m_base + gid + 8][ks + tig]);
            unsigned int a2 = f2tf(As[buf][m_base + gid][ks + tig + 4]);
            unsigned int a3 = f2tf(As[buf][m_base + gid + 8][ks + tig + 4]);
            unsigned int bb0 = f2tf(Bs[buf][ks + tig][n_base + gid]);
            unsigned int bb1 = f2tf(Bs[buf][ks + tig + 4][n_base + gid]);
            unsigned int bb2 = f2tf(Bs[buf][ks + tig][n_base + 8 + gid]);
            unsigned int bb3 = f2tf(Bs[buf][ks + tig + 4][n_base + 8 + gid]);
            mma_tf32(acc0, a0, a1, a2, a3, bb0, bb1);
            mma_tf32(acc1, a0, a1, a2, a3, bb2, bb3);
        }
        __syncthreads();
    }

    // epilogue: warp tile rows gid, gid+8; cols tig*2, tig*2+1 per n-subtile
    const int row = blockIdx.y * 32 + m_base + gid;
    #pragma unroll
    for (int nt = 0; nt < 2; ++nt) {
        const float* accp = nt ? acc1 : acc0;
        const int col = blockIdx.x * 64 + n_base + nt * 8 + tig * 2;
        float2 bv = make_float2(0.f, 0.f);
        if (bias) bv = *(const float2*)(bias + col);
        float2 o0, o1;
        o0.x = accp[0] + bv.x; o0.y = accp[1] + bv.y;
        o1.x = accp[2] + bv.x; o1.y = accp[3] + bv.y;
        if (RELU) {
            o0.x = fmaxf(o0.x, 0.f); o0.y = fmaxf(o0.y, 0.f);
            o1.x = fmaxf(o1.x, 0.f); o1.y = fmaxf(o1.y, 0.f);
        }
        *(float2*)(C + (size_t)row * N + col) = o0;
        *(float2*)(C + (size_t)(row + 8) * N + col) = o1;
    }
}

// --------------------------------------------------- fused attention row
__global__ void __launch_bounds__(384) k_attn(int l) {
    __shared__ float s_logit[NR * NH];   // 24 KB
    __shared__ uint4 s_zu[1024];         // 16 KB: fp16 z tile / reduction scratch
    __shared__ float s_ms[NR];
    __shared__ float s_q[DQ];

    const int i = blockIdx.x;
    const int t = threadIdx.x;

    if (t < DQ) s_q[t] = g_buf[OFF_Q + i * DQ + t];
    const float cx = g_buf[OFF_CO + i * 3 + 0];
    const float cy = g_buf[OFF_CO + i * 3 + 1];
    const float cz2 = g_buf[OFF_CO + i * 3 + 2];
    for (int j = t; j < NR; j += 384) {
        float dx = g_buf[OFF_CO + j * 3 + 0] - cx;
        float dy = g_buf[OFF_CO + j * 3 + 1] - cy;
        float dz = g_buf[OFF_CO + j * 3 + 2] - cz2;
        float sq = dx * dx + dy * dy + dz * dz;
        s_ms[j] = (sq <= 25.f) ? 1.f : ((sq <= 225.f) ? 0.3f : 0.05f);
    }
    __syncthreads();

    const __half* K16 = (const __half*)(g_buf + OFF_KV16);
    const __half* V16 = K16 + NR * DQ;
    const __half* bias16 = (const __half*)(g_buf + OFF_B)
                           + (size_t)l * BIAS_LH + (size_t)i * (NR * NH);

    // logits = q.k/4 + bias_z + ms   (fp16 K, fp16 bias)
    #pragma unroll 4
    for (int idx = t; idx < NR * NH; idx += 384) {
        int j = idx / 12, h = idx - j * 12;
        const uint4* kp = (const uint4*)(K16 + j * DQ + h * CH);
        uint4 ka = kp[0], kb = kp[1];
        const __half2* k2a = (const __half2*)&ka;
        const __half2* k2b = (const __half2*)&kb;
        const float2* qp = (const float2*)(s_q + h * CH);
        float d = 0.f;
        #pragma unroll
        for (int u = 0; u < 4; ++u) {
            float2 kf = __half22float2(k2a[u]);
            float2 qf = qp[u];
            d = fmaf(kf.x, qf.x, d); d = fmaf(kf.y, qf.y, d);
        }
        #pragma unroll
        for (int u = 0; u < 4; ++u) {
            float2 kf = __half22float2(k2b[u]);
            float2 qf = qp[4 + u];
            d = fmaf(kf.x, qf.x, d); d = fmaf(kf.y, qf.y, d);
        }
        s_logit[idx] = fmaf(d, 0.25f, __half2float(bias16[idx]) + s_ms[j]);
    }
    __syncthreads();

    // softmax over j, warp per head
    {
        int h = t >> 5, lane = t & 31;
        float m = -1e30f;
        for (int j = lane; j < NR; j += 32) m = fmaxf(m, s_logit[j * 12 + h]);
        #pragma unroll
        for (int o = 16; o; o >>= 1) m = fmaxf(m, __shfl_xor_sync(0xffffffffu, m, o));
        float ssum = 0.f;
        for (int j = lane; j < NR; j += 32) {
            float e = __expf(s_logit[j * 12 + h] - m);
            s_logit[j * 12 + h] = e; ssum += e;
        }
        #pragma unroll
        for (int o = 16; o; o >>= 1) ssum += __shfl_xor_sync(0xffffffffu, ssum, o);
        float inv = 1.f / ssum;
        for (int j = lane; j < NR; j += 32) s_logit[j * 12 + h] *= inv;
    }

    // pair[h][c] = sum_j w[j][h] * z[i,j,c] — fp16 z staged in smem tiles
    {
        const int c = t & 127, jg = t >> 7;
        float pa[12] = {};
        const __half* z16 = (const __half*)(g_buf + OFF_Z16);
        const size_t zrow = (size_t)i * (NR * CZ);
        #pragma unroll 1
        for (int tile = 0; tile < 8; ++tile) {
            __syncthreads();
            const uint4* src = (const uint4*)(z16 + zrow + (size_t)tile * 64 * CZ);
            #pragma unroll
            for (int v2 = 0; v2 < 3; ++v2) {
                int v = t + v2 * 384;
                if (v < 1024) s_zu[v] = src[v];
            }
            __syncthreads();
            const __half* zt = (const __half*)s_zu;
            const float* wbase = s_logit + tile * 64 * 12;
            for (int lj = jg; lj < 64; lj += 3) {
                float zv = __half2float(zt[lj * CZ + c]);
                const float4* wr = (const float4*)(wbase + lj * 12);
                float4 w0 = wr[0], w1 = wr[1], w2 = wr[2];
                pa[0] = fmaf(w0.x, zv, pa[0]);  pa[1] = fmaf(w0.y, zv, pa[1]);
                pa[2] = fmaf(w0.z, zv, pa[2]);  pa[3] = fmaf(w0.w, zv, pa[3]);
                pa[4] = fmaf(w1.x, zv, pa[4]);  pa[5] = fmaf(w1.y, zv, pa[5]);
                pa[6] = fmaf(w1.z, zv, pa[6]);  pa[7] = fmaf(w1.w, zv, pa[7]);
                pa[8] = fmaf(w2.x, zv, pa[8]);  pa[9] = fmaf(w2.y, zv, pa[9]);
                pa[10] = fmaf(w2.z, zv, pa[10]); pa[11] = fmaf(w2.w, zv, pa[11]);
            }
        }
        __syncthreads();
        float* s_redf = (float*)s_zu;
        if (jg) {
            #pragma unroll
            for (int h = 0; h < 12; ++h) s_redf[((jg - 1) * 128 + c) * 12 + h] = pa[h];
        }
        __syncthreads();
        if (jg == 0) {
            #pragma unroll
            for (int h = 0; h < 12; ++h)
                g_buf[OFF_O + i * DO + h * 144 + 16 + c] =
                    pa[h] + s_redf[c * 12 + h] + s_redf[(128 + c) * 12 + h];
        }
    }

    // scalar[h][c] = sum_j w[j][h] * v[j,h,c] — fp16 V, warp per head
    {
        const int h = t >> 5, lane = t & 31;
        const int part = lane >> 3, c2 = lane & 7;
        const __half2* vp = (const __half2*)(V16 + h * CH) + c2;
        float2 acc2 = make_float2(0.f, 0.f);
        #pragma unroll 8
        for (int j = part; j < NR; j += 4) {
            float w = s_logit[j * 12 + h];
            float2 vf = __half22float2(vp[j * (DQ / 2)]);
            acc2.x = fmaf(w, vf.x, acc2.x);
            acc2.y = fmaf(w, vf.y, acc2.y);
        }
        acc2.x += __shfl_xor_sync(0xffffffffu, acc2.x, 8);
        acc2.y += __shfl_xor_sync(0xffffffffu, acc2.y, 8);
        acc2.x += __shfl_xor_sync(0xffffffffu, acc2.x, 16);
        acc2.y += __shfl_xor_sync(0xffffffffu, acc2.y, 16);
        if (lane < 8) *(float2*)(g_buf + OFF_O + i * DO + h * 144 + c2 * 2) = acc2;
    }
}

// --------------------------- layernorm over (s + c0 + c1 + c2), + coords
__global__ void __launch_bounds__(128) k_ln(const float* __restrict__ g,
                                            const float* __restrict__ b,
                                            const float* __restrict__ Wu,
                                            const float* __restrict__ bu,
                                            int fuse) {
    const int i = blockIdx.x, t = threadIdx.x, base = i * CS;

    float x0 = g_buf[OFF_S + base + t]       + g_buf[OFF_C + base + t]
             + g_buf[OFF_C2 + base + t]      + g_buf[OFF_C3 + base + t];
    float x1 = g_buf[OFF_S + base + t + 128] + g_buf[OFF_C + base + t + 128]
             + g_buf[OFF_C2 + base + t + 128] + g_buf[OFF_C3 + base + t + 128];
    float x2 = g_buf[OFF_S + base + t + 256] + g_buf[OFF_C + base + t + 256]
             + g_buf[OFF_C2 + base + t + 256] + g_buf[OFF_C3 + base + t + 256];

    float sum = x0 + x1 + x2;
    float sq  = x0 * x0 + x1 * x1 + x2 * x2;
    #pragma unroll
    for (int o = 16; o; o >>= 1) {
        sum += __shfl_xor_sync(0xffffffffu, sum, o);
        sq  += __shfl_xor_sync(0xffffffffu, sq, o);
    }
    __shared__ float sred[8];
    const int w = t >> 5, lane = t & 31;
    if (lane == 0) { sred[w] = sum; sred[4 + w] = sq; }
    __syncthreads();
    sum = sred[0] + sred[1] + sred[2] + sred[3];
    sq  = sred[4] + sred[5] + sred[6] + sred[7];
    float mu  = sum * (1.f / CS);
    float var = sq * (1.f / CS) - mu * mu;
    float rs  = rsqrtf(var + 1e-5f);

    float y0 = (x0 - mu) * rs * g[t]       + b[t];
    float y1 = (x1 - mu) * rs * g[t + 128] + b[t + 128];
    float y2 = (x2 - mu) * rs * g[t + 256] + b[t + 256];
    g_buf[OFF_S + base + t]       = y0;
    g_buf[OFF_S + base + t + 128] = y1;
    g_buf[OFF_S + base + t + 256] = y2;

    if (fuse) {
        float p0 = y0 * Wu[t * 6 + 0] + y1 * Wu[(t + 128) * 6 + 0] + y2 * Wu[(t + 256) * 6 + 0];
        float p1 = y0 * Wu[t * 6 + 1] + y1 * Wu[(t + 128) * 6 + 1] + y2 * Wu[(t + 256) * 6 + 1];
        float p2 = y0 * Wu[t * 6 + 2] + y1 * Wu[(t + 128) * 6 + 2] + y2 * Wu[(t + 256) * 6 + 2];
        #pragma unroll
        for (int o = 16; o; o >>= 1) {
            p0 += __shfl_xor_sync(0xffffffffu, p0, o);
            p1 += __shfl_xor_sync(0xffffffffu, p1, o);
            p2 += __shfl_xor_sync(0xffffffffu, p2, o);
        }
        __shared__ float sp[12];
        if (lane == 0) { sp[w] = p0; sp[4 + w] = p1; sp[8 + w] = p2; }
        __syncthreads();
        if (t == 0) {
            g_buf[OFF_CO + i * 3 + 0] += sp[0] + sp[1] + sp[2]  + sp[3]  + bu[0];
            g_buf[OFF_CO + i * 3 + 1] += sp[4] + sp[5] + sp[6]  + sp[7]  + bu[1];
            g_buf[OFF_CO + i * 3 + 2] += sp[8] + sp[9] + sp[10] + sp[11] + bu[2];
        }
    }
}

__global__ void k_out(float* __restrict__ out) {
    int i = blockIdx.x * blockDim.x + threadIdx.x;
    if (i < NR * 3) out[i] = g_buf[OFF_CO + i];
}

// ---------------------------------------------------------------- launch
extern "C" void kernel_launch(void* const* d_in, const int* in_sizes, int n_in,
                              void* d_out, int out_size) {
    const float* s   = (const float*)d_in[0];
    const float* z   = (const float*)d_in[1];
    const float* Wq  = (const float*)d_in[2];
    const float* bq  = (const float*)d_in[3];
    const float* Wk  = (const float*)d_in[4];
    const float* bk  = (const float*)d_in[5];
    const float* Wv  = (const float*)d_in[6];
    const float* bv  = (const float*)d_in[7];
    const float* Wb  = (const float*)d_in[8];
    const float* bb  = (const float*)d_in[9];
    const float* Wo  = (const float*)d_in[10];
    const float* bo  = (const float*)d_in[11];
    const float* Wt1 = (const float*)d_in[12];
    const float* bt1 = (const float*)d_in[13];
    const float* Wt2 = (const float*)d_in[14];
    const float* bt2 = (const float*)d_in[15];
    const float* Wu  = (const float*)d_in[16];
    const float* bu  = (const float*)d_in[17];
    const float* lng = (const float*)d_in[18];
    const float* lnb = (const float*)d_in[19];

    k_init<<<768, 256>>>(s);
    k_z16<<<32768, 256>>>(z);
    k_biaspre<<<dim3(1024, 2), 128>>>(z, Wb, bb);

    for (int r = 0; r < 2; ++r) {
        for (int l = 0; l < 8; ++l) {
            // qkv: 3 weight sets
            k_gemm<0, 0><<<dim3(3, 16, 3), 256>>>(OFF_S,
                Wq + (size_t)l * CS * DQ, Wk + (size_t)l * CS * DQ, Wv + (size_t)l * CS * DQ,
                bq + l * DQ, bk + l * DQ, bv + l * DQ,
                OFF_Q, NR * DQ, CS, CS, DQ);
            k_kv16<<<192, 256>>>();
            k_attn<<<512, 384>>>(l);
            // Wo: K=1728, split-K=3
            k_gemm<0, 1><<<dim3(6, 16, 3), 256>>>(OFF_O,
                Wo + (size_t)l * DO * CS, nullptr, nullptr,
                bo + l * CS, nullptr, nullptr,
                OFF_C, OFF_C2 - OFF_C, DO, DO / 3, CS);
            k_ln<<<512, 128>>>(lng + (2 * l) * CS, lnb + (2 * l) * CS, nullptr, nullptr, 0);
            // FFN1: N=1536, ReLU
            k_gemm<1, 0><<<dim3(24, 16, 1), 256>>>(OFF_S,
                Wt1 + (size_t)l * CS * DF, nullptr, nullptr,
                bt1 + l * DF, nullptr, nullptr,
                OFF_T, 0, CS, CS, DF);
            // FFN2: K=1536, split-K=3
            k_gemm<0, 1><<<dim3(6, 16, 3), 256>>>(OFF_T,
                Wt2 + (size_t)l * DF * CS, nullptr, nullptr,
                bt2 + l * CS, nullptr, nullptr,
                OFF_C, OFF_C2 - OFF_C, DF, DF / 3, CS);
            k_ln<<<512, 128>>>(lng + (2 * l + 1) * CS, lnb + (2 * l + 1) * CS,
                               Wu + (size_t)l * CS * 6, bu + l * 6, 1);
        }
    }
    k_out<<<6, 256>>>((float*)d_out);
}